// round 6
// baseline (speedup 1.0000x reference)
#include <cuda_runtime.h>

#define BQ 4096
#define NS 8192
#define NSH (NS / 2)         // samples per half
#define DD 256
#define BM 64
#define BN 64
#define XST 260              // padded row stride (floats); 1040B, 16B-aligned, conflict-free phases
#define PST 72               // P tile stride: GEMM2 P reads conflict-free
#define NTHREADS 256
#define NTILES (NSH / BN)    // 64 tiles per half

#define SMEM_FLOATS (BM * XST + 2 * BN * XST + BM * PST + 5 * BM)
#define SMEM_BYTES (SMEM_FLOATS * 4)

__device__ float g_s2half[NS];
__device__ float g_m[2 * BQ];
__device__ float g_l[2 * BQ];
__device__ float g_O[2 * BQ * DD];

static __device__ __forceinline__ unsigned long long ffma2(unsigned long long a,
                                                           unsigned long long b,
                                                           unsigned long long c) {
    unsigned long long d;
    asm("fma.rn.f32x2 %0, %1, %2, %3;" : "=l"(d) : "l"(a), "l"(b), "l"(c));
    return d;
}
static __device__ __forceinline__ unsigned long long fmul2(unsigned long long a,
                                                           unsigned long long b) {
    unsigned long long d;
    asm("mul.rn.f32x2 %0, %1, %2;" : "=l"(d) : "l"(a), "l"(b));
    return d;
}
static __device__ __forceinline__ unsigned long long pk2(float lo, float hi) {
    unsigned long long r;
    asm("mov.b64 %0, {%1, %2};" : "=l"(r) : "f"(lo), "f"(hi));
    return r;
}
static __device__ __forceinline__ float lo2(unsigned long long v) {
    return __uint_as_float((unsigned)v);
}
static __device__ __forceinline__ float hi2(unsigned long long v) {
    return __uint_as_float((unsigned)(v >> 32));
}

#define CP_ASYNC16(dst_u32, src_ptr)                                        \
    asm volatile("cp.async.cg.shared.global [%0], [%1], 16;" ::"r"(dst_u32), \
                 "l"(src_ptr))
#define CP_COMMIT() asm volatile("cp.async.commit_group;" ::: "memory")
#define CP_WAIT1() asm volatile("cp.async.wait_group 1;" ::: "memory")

// 0.5 * ||s_n||^2, one warp per sample
__global__ void s2_kernel(const float* __restrict__ samples) {
    int w = (blockIdx.x * blockDim.x + threadIdx.x) >> 5;
    int lane = threadIdx.x & 31;
    if (w >= NS) return;
    const float* row = samples + (size_t)w * DD;
    float s = 0.f;
    #pragma unroll
    for (int i = 0; i < DD / 32; i++) {
        float v = row[lane + 32 * i];
        s = fmaf(v, v, s);
    }
    #pragma unroll
    for (int o = 16; o; o >>= 1) s += __shfl_xor_sync(0xffffffffu, s, o);
    if (lane == 0) g_s2half[w] = 0.5f * s;
}

__global__ __launch_bounds__(NTHREADS, 1) void score_part(
    const float* __restrict__ tvec, const float* __restrict__ x,
    const float* __restrict__ samples) {
    extern __shared__ float smem[];
    float* sX = smem;                      // BM x XST
    float* sK0 = sX + BM * XST;            // BN x XST (double buffered)
    float* sK1 = sK0 + BN * XST;
    float* sP = sK1 + BN * XST;            // BM x PST
    float* sInvd = sP + BM * PST;
    float* sM = sInvd + BM;
    float* sL = sM + BM;
    float* sAl = sL + BM;
    float* sS2 = sAl + BM;

    const int tid = threadIdx.x;
    const int qblk = blockIdx.x >> 1;
    const int h = blockIdx.x & 1;
    const int qbase = qblk * BM;
    const int nbase0 = h * NSH;

    const int ty = tid >> 4;  // 0..15 : query row group {ty, ty+16, ty+32, ty+48}
    const int tx = tid & 15;  // 0..15 : col group (GEMM1) / d-chunk (GEMM2)

    // ---- load X tile (64 x 256) ----
    #pragma unroll
    for (int r = 0; r < (BM * DD / 4) / NTHREADS; r++) {
        int idx = tid + NTHREADS * r;
        int row = idx >> 6, c4 = idx & 63;
        float4 v = *(const float4*)(x + (size_t)(qbase + row) * DD + c4 * 4);
        *(float4*)(sX + row * XST + c4 * 4) = v;
    }
    if (tid < BM) {
        float tt = tvec[qbase + tid];
        float ts = 0.01f * exp2f(tt * 13.287712379549449f);
        float dn = fmaf(ts, ts, 1e-8f);
        sInvd[tid] = 1.0f / dn;
        sM[tid] = __int_as_float(0xff800000);
        sL[tid] = 0.0f;
    }

    // prefetch K tile 0
    {
        unsigned int kdst = (unsigned int)__cvta_generic_to_shared(sK0);
        const float* gsrc = samples + (size_t)nbase0 * DD;
        #pragma unroll
        for (int r = 0; r < (BN * DD / 4) / NTHREADS; r++) {
            int idx = tid + NTHREADS * r;
            int row = idx >> 6, c4 = idx & 63;
            CP_ASYNC16(kdst + (row * XST + c4 * 4) * 4, gsrc + row * DD + c4 * 4);
        }
    }
    CP_COMMIT();

    unsigned long long O2[4][8];  // 4 rows x 16 floats (packed)
    #pragma unroll
    for (int i = 0; i < 4; i++)
        #pragma unroll
        for (int j = 0; j < 8; j++) O2[i][j] = 0ull;

    for (int kt = 0; kt < NTILES; kt++) {
        float* sKc = (kt & 1) ? sK1 : sK0;
        // prefetch next tile into the other buffer
        if (kt + 1 < NTILES) {
            float* sKn = (kt & 1) ? sK0 : sK1;
            unsigned int kdst = (unsigned int)__cvta_generic_to_shared(sKn);
            const float* gsrc = samples + (size_t)(nbase0 + (kt + 1) * BN) * DD;
            #pragma unroll
            for (int r = 0; r < (BN * DD / 4) / NTHREADS; r++) {
                int idx = tid + NTHREADS * r;
                int row = idx >> 6, c4 = idx & 63;
                CP_ASYNC16(kdst + (row * XST + c4 * 4) * 4, gsrc + row * DD + c4 * 4);
            }
        }
        CP_COMMIT();
        CP_WAIT1();
        if (tid < BN) sS2[tid] = g_s2half[nbase0 + kt * BN + tid];
        __syncthreads();

        // ---- GEMM1: S[4][4] = X @ K^T (4x4 micro-tile, packed f32x2) ----
        unsigned long long acc[16];
        #pragma unroll
        for (int j = 0; j < 16; j++) acc[j] = 0ull;
        {
            const ulonglong2* Xr[4];
            const ulonglong2* Kr[4];
            #pragma unroll
            for (int i = 0; i < 4; i++) {
                Xr[i] = (const ulonglong2*)(sX + (ty + 16 * i) * XST);
                Kr[i] = (const ulonglong2*)(sKc + (tx + 16 * i) * XST);
            }
            #pragma unroll 4
            for (int g = 0; g < DD / 4; g++) {
                ulonglong2 av[4], bv[4];
                #pragma unroll
                for (int i = 0; i < 4; i++) av[i] = Xr[i][g];
                #pragma unroll
                for (int i = 0; i < 4; i++) bv[i] = Kr[i][g];
                #pragma unroll
                for (int i = 0; i < 4; i++)
                    #pragma unroll
                    for (int j = 0; j < 4; j++) {
                        acc[i * 4 + j] = ffma2(av[i].x, bv[j].x, acc[i * 4 + j]);
                        acc[i * 4 + j] = ffma2(av[i].y, bv[j].y, acc[i * 4 + j]);
                    }
            }
        }

        // ---- online softmax (per thread: 4 rows x 4 cols) ----
        float s2c[4];
        #pragma unroll
        for (int j = 0; j < 4; j++) s2c[j] = sS2[tx + 16 * j];

        float al[4];
        #pragma unroll
        for (int i = 0; i < 4; i++) {
            int row = ty + 16 * i;
            float invd = sInvd[row];
            float lg[4];
            #pragma unroll
            for (int j = 0; j < 4; j++) {
                float dot = (lo2(acc[i * 4 + j]) + hi2(acc[i * 4 + j]));
                lg[j] = (dot - s2c[j]) * invd;
            }
            float rmax = fmaxf(fmaxf(lg[0], lg[1]), fmaxf(lg[2], lg[3]));
            #pragma unroll
            for (int o = 8; o; o >>= 1)
                rmax = fmaxf(rmax, __shfl_xor_sync(0xffffffffu, rmax, o));
            float mold = sM[row];
            float mnew = fmaxf(mold, rmax);
            float p0 = __expf(lg[0] - mnew), p1 = __expf(lg[1] - mnew);
            float p2 = __expf(lg[2] - mnew), p3 = __expf(lg[3] - mnew);
            float rs = (p0 + p1) + (p2 + p3);
            #pragma unroll
            for (int o = 8; o; o >>= 1) rs += __shfl_xor_sync(0xffffffffu, rs, o);
            sP[row * PST + tx] = p0;
            sP[row * PST + tx + 16] = p1;
            sP[row * PST + tx + 32] = p2;
            sP[row * PST + tx + 48] = p3;
            float a = __expf(mold - mnew);
            al[i] = a;
            if (tx == 0) {
                sM[row] = mnew;
                sL[row] = sL[row] * a + rs;
                sAl[row] = a;
            }
        }
        __syncthreads();

        // ---- GEMM2: O += P @ K (4 rows/thread share K loads) ----
        #pragma unroll
        for (int i = 0; i < 4; i++) {
            float a = al[i];  // own-warp row: register value is the true alpha
            if (a != 1.0f) {
                unsigned long long a2 = pk2(a, a);
                #pragma unroll
                for (int j = 0; j < 8; j++) O2[i][j] = fmul2(O2[i][j], a2);
            }
        }
        {
            const float* Pb = sP + ty * PST;
            #pragma unroll 2
            for (int k = 0; k < BN; k++) {
                const ulonglong2* Kr = (const ulonglong2*)(sKc + k * XST) + tx;
                ulonglong2 kv[4];
                #pragma unroll
                for (int j = 0; j < 4; j++) kv[j] = Kr[16 * j];
                #pragma unroll
                for (int i = 0; i < 4; i++) {
                    float p = Pb[16 * i * PST + k];
                    unsigned long long p2 = pk2(p, p);
                    #pragma unroll
                    for (int j = 0; j < 4; j++) {
                        O2[i][2 * j] = ffma2(p2, kv[j].x, O2[i][2 * j]);
                        O2[i][2 * j + 1] = ffma2(p2, kv[j].y, O2[i][2 * j + 1]);
                    }
                }
            }
        }
        __syncthreads();
    }

    // ---- store partials: unnormalized O, plus (m, l) per row ----
    #pragma unroll
    for (int i = 0; i < 4; i++) {
        int row = ty + 16 * i;
        int q = qbase + row;
        float* orow = g_O + ((size_t)h * BQ + q) * DD;
        #pragma unroll
        for (int j = 0; j < 4; j++) {
            float4 o;
            o.x = lo2(O2[i][2 * j]);
            o.y = hi2(O2[i][2 * j]);
            o.z = lo2(O2[i][2 * j + 1]);
            o.w = hi2(O2[i][2 * j + 1]);
            *(float4*)(orow + 4 * tx + 64 * j) = o;
        }
        if (tx == 0) {
            g_m[h * BQ + q] = sM[row];
            g_l[h * BQ + q] = sL[row];
        }
    }
}

// merge the two halves + epilogue
__global__ void combine_kernel(const float* __restrict__ tvec,
                               const float* __restrict__ x,
                               float* __restrict__ out) {
    int idx = blockIdx.x * blockDim.x + threadIdx.x;  // over BQ * 64 float4
    int q = idx >> 6, c4 = idx & 63;
    float m0 = g_m[q], m1 = g_m[BQ + q];
    float l0 = g_l[q], l1 = g_l[BQ + q];
    float m = fmaxf(m0, m1);
    float e0 = __expf(m0 - m), e1 = __expf(m1 - m);
    float linv = 1.0f / (l0 * e0 + l1 * e1);
    float w0 = e0 * linv, w1 = e1 * linv;

    float tt = tvec[q];
    float ts = 0.01f * exp2f(tt * 13.287712379549449f);
    float scale = ts / fmaf(ts, ts, 1e-8f);

    float4 o0 = *(const float4*)(g_O + (size_t)q * DD + c4 * 4);
    float4 o1 = *(const float4*)(g_O + ((size_t)BQ + q) * DD + c4 * 4);
    float4 xx = *(const float4*)(x + (size_t)q * DD + c4 * 4);
    float4 r;
    r.x = (o0.x * w0 + o1.x * w1 - xx.x) * scale;
    r.y = (o0.y * w0 + o1.y * w1 - xx.y) * scale;
    r.z = (o0.z * w0 + o1.z * w1 - xx.z) * scale;
    r.w = (o0.w * w0 + o1.w * w1 - xx.w) * scale;
    *(float4*)(out + (size_t)q * DD + c4 * 4) = r;
}

extern "C" void kernel_launch(void* const* d_in, const int* in_sizes, int n_in,
                              void* d_out, int out_size) {
    const float* t = nullptr;
    const float* x = nullptr;
    const float* s = nullptr;
    for (int i = 0; i < n_in; i++) {
        if (in_sizes[i] == BQ) t = (const float*)d_in[i];
        else if (in_sizes[i] == BQ * DD) x = (const float*)d_in[i];
        else if (in_sizes[i] == NS * DD) s = (const float*)d_in[i];
    }
    float* out = (float*)d_out;

    s2_kernel<<<NS / 8, 256>>>(s);

    cudaFuncSetAttribute(score_part, cudaFuncAttributeMaxDynamicSharedMemorySize,
                         SMEM_BYTES);
    score_part<<<(BQ / BM) * 2, NTHREADS, SMEM_BYTES>>>(t, x, s);

    combine_kernel<<<BQ * (DD / 4) / 256, 256>>>(t, x, out);
}

// round 12
// speedup vs baseline: 1.5503x; 1.5503x over previous
#include <cuda_runtime.h>

typedef unsigned int u32;
typedef unsigned long long u64;

#define BQ 4096
#define NS 8192
#define DD 256
#define NSPLIT 4
#define KSP (NS / NSPLIT)   // 2048 samples per split-K CTA

// ---------------- static scratch ----------------
__device__ float g_Xh[BQ * DD];
__device__ float g_Xl[BQ * DD];
__device__ float g_Sh[NS * DD];
__device__ float g_Sl[NS * DD];
__device__ float g_ST[DD * NS];    // transposed samples, tf32-rounded (high)
__device__ float g_STl[DD * NS];   // transposed samples residual (tf32-rounded)
__device__ float g_s2half[NS];
__device__ float g_invd[BQ];
__device__ unsigned g_mU[BQ];      // monotone-mapped row max
__device__ float g_l[BQ];
__device__ float g_S[(long long)BQ * NS];   // logits, then P (in place)
__device__ float g_Op[NSPLIT][BQ * DD];

// ---------------- helpers ----------------
static __device__ __forceinline__ u32 smem_u32(const void* p) {
    return (u32)__cvta_generic_to_shared(p);
}
static __device__ __forceinline__ float to_tf32(float v) {
    float r;
    asm("cvt.rna.tf32.f32 %0, %1;" : "=f"(r) : "f"(v));
    return r;
}
static __device__ __forceinline__ unsigned fmap(float v) {
    unsigned u = __float_as_uint(v);
    return (u & 0x80000000u) ? ~u : (u | 0x80000000u);
}

#define CP_ASYNC16(dst_u32, src_ptr)                                         \
    asm volatile("cp.async.cg.shared.global [%0], [%1], 16;" ::"r"(dst_u32), \
                 "l"(src_ptr))
#define CP_COMMIT() asm volatile("cp.async.commit_group;" ::: "memory")
#define CP_WAIT1() asm volatile("cp.async.wait_group 1;" ::: "memory")
#define CP_WAIT0() asm volatile("cp.async.wait_group 0;" ::: "memory")

// m16n8k8 tf32 mma: D += A*B  (A row-major m16k8, B col-major k8n8)
#define MMA_TF32(d, a, b)                                                   \
    asm volatile(                                                           \
        "mma.sync.aligned.m16n8k8.row.col.f32.tf32.tf32.f32 "               \
        "{%0,%1,%2,%3}, {%4,%5,%6,%7}, {%8,%9}, {%0,%1,%2,%3};"             \
        : "+f"((d)[0]), "+f"((d)[1]), "+f"((d)[2]), "+f"((d)[3])            \
        : "r"(__float_as_uint((a)[0])), "r"(__float_as_uint((a)[1])),       \
          "r"(__float_as_uint((a)[2])), "r"(__float_as_uint((a)[3])),       \
          "r"(__float_as_uint((b)[0])), "r"(__float_as_uint((b)[1])))

// padded row stride 36: word index (36r + c) mod 32 = (4r + c) mod 32 ->
// 8 rows x 4 cols hit 32 distinct banks: conflict-free fragment gathers.
#define KCP 36
#define TILE_F (128 * KCP)  // 4608 floats per 128x32 tile

// ---------------- prep kernels ----------------
__global__ void init_kernel(const float* __restrict__ tvec) {
    int q = blockIdx.x * 256 + threadIdx.x;
    float tt = tvec[q];
    float ts = 0.01f * exp2f(tt * 13.287712379549449f);
    g_invd[q] = 1.0f / fmaf(ts, ts, 1e-8f);
    g_mU[q] = 0u;
}

__global__ void split_x_kernel(const float* __restrict__ x) {
    int i = blockIdx.x * 256 + threadIdx.x;
    float v = x[i];
    float h = to_tf32(v);
    g_Xh[i] = h;
    g_Xl[i] = to_tf32(v - h);
}

__global__ void split_s_kernel(const float* __restrict__ s) {
    int i = blockIdx.x * 256 + threadIdx.x;
    float v = s[i];
    float h = to_tf32(v);
    g_Sh[i] = h;
    g_Sl[i] = to_tf32(v - h);
}

__global__ void transpose_kernel(const float* __restrict__ s) {
    __shared__ float T[32][33];
    int s0 = blockIdx.x * 32, d0 = blockIdx.y * 32;
    int tx = threadIdx.x, ty = threadIdx.y;  // (32, 8)
    #pragma unroll
    for (int j = 0; j < 32; j += 8)
        T[ty + j][tx] = s[(long long)(s0 + ty + j) * DD + d0 + tx];
    __syncthreads();
    #pragma unroll
    for (int j = 0; j < 32; j += 8) {
        float v = T[tx][ty + j];
        float h = to_tf32(v);
        long long o = (long long)(d0 + ty + j) * NS + s0 + tx;
        g_ST[o] = h;
        g_STl[o] = to_tf32(v - h);
    }
}

__global__ void s2_kernel(const float* __restrict__ samples) {
    int w = (blockIdx.x * blockDim.x + threadIdx.x) >> 5;
    int lane = threadIdx.x & 31;
    if (w >= NS) return;
    const float* row = samples + (size_t)w * DD;
    float s = 0.f;
    #pragma unroll
    for (int i = 0; i < DD / 32; i++) {
        float v = row[lane + 32 * i];
        s = fmaf(v, v, s);
    }
    #pragma unroll
    for (int o = 16; o; o >>= 1) s += __shfl_xor_sync(0xffffffffu, s, o);
    if (lane == 0) g_s2half[w] = 0.5f * s;
}

// ---------------- GEMM1: logits = (X @ S^T - s2half) * invd ----------------
// CTA tile: 128 q x 128 n, K=256 in 8 chunks of 32. tf32 3-product split.
// smem buffer layout (floats): Ah[TILE_F] Al[TILE_F] Bh[TILE_F] Bl[TILE_F]
#define G1_BUF (4 * TILE_F)                     // 18432 floats
#define G1_SMEM ((2 * G1_BUF + 256) * 4)        // + sInvd/sS2

static __device__ __forceinline__ void g1_load(int tid, float* buf, int qbase,
                                               int nbase, int kb) {
    u32 b = smem_u32(buf);
    #pragma unroll
    for (int it = 0; it < 16; it++) {
        int i = tid + it * 256;
        int sec = i >> 10, j = i & 1023;
        int row = j >> 3, c = (j & 7) * 4;
        const float* src;
        if (sec == 0)      src = g_Xh + (size_t)(qbase + row) * DD + kb + c;
        else if (sec == 1) src = g_Xl + (size_t)(qbase + row) * DD + kb + c;
        else if (sec == 2) src = g_Sh + (size_t)(nbase + row) * DD + kb + c;
        else               src = g_Sl + (size_t)(nbase + row) * DD + kb + c;
        CP_ASYNC16(b + (u32)((sec * TILE_F + row * KCP + c) * 4), src);
    }
}

__global__ __launch_bounds__(256, 1) void gemm1_kernel() {
    extern __shared__ float sm[];
    float* sInvd = sm + 2 * G1_BUF;
    float* sS2 = sInvd + 128;
    const int tid = threadIdx.x;
    const int qt = blockIdx.x >> 6, nt = blockIdx.x & 63;
    const int qbase = qt * 128, nbase = nt * 128;

    if (tid < 128) {
        sInvd[tid] = g_invd[qbase + tid];
        sS2[tid] = g_s2half[nbase + tid];
    }
    g1_load(tid, sm, qbase, nbase, 0);
    CP_COMMIT();

    const int wid = tid >> 5, lane = tid & 31;
    const int wm = wid >> 1, wn = wid & 1;
    const int gr = lane >> 2, lc = lane & 3;

    float acc[2][8][4];
    #pragma unroll
    for (int mb = 0; mb < 2; mb++)
        #pragma unroll
        for (int nb = 0; nb < 8; nb++)
            #pragma unroll
            for (int e = 0; e < 4; e++) acc[mb][nb][e] = 0.f;

    for (int s = 0; s < 8; s++) {
        float* buf = sm + (s & 1) * G1_BUF;
        if (s + 1 < 8) {
            g1_load(tid, sm + ((s + 1) & 1) * G1_BUF, qbase, nbase, (s + 1) * 32);
            CP_COMMIT();
            CP_WAIT1();
        } else {
            CP_WAIT0();
        }
        __syncthreads();
        const float* Ah = buf;
        const float* Al = buf + TILE_F;
        const float* Bh = buf + 2 * TILE_F;
        const float* Bl = buf + 3 * TILE_F;
        #pragma unroll
        for (int ks = 0; ks < 4; ks++) {
            int k0 = ks * 8;
            float ah[2][4], al[2][4];
            #pragma unroll
            for (int mb = 0; mb < 2; mb++) {
                int o0 = (wm * 32 + mb * 16 + gr) * KCP + k0 + lc;
                ah[mb][0] = Ah[o0];           ah[mb][1] = Ah[o0 + 8 * KCP];
                ah[mb][2] = Ah[o0 + 4];       ah[mb][3] = Ah[o0 + 8 * KCP + 4];
                al[mb][0] = Al[o0];           al[mb][1] = Al[o0 + 8 * KCP];
                al[mb][2] = Al[o0 + 4];       al[mb][3] = Al[o0 + 8 * KCP + 4];
            }
            float bh[8][2], bl[8][2];
            #pragma unroll
            for (int nb = 0; nb < 8; nb++) {
                int o = (wn * 64 + nb * 8 + gr) * KCP + k0 + lc;
                bh[nb][0] = Bh[o];
                bh[nb][1] = Bh[o + 4];
                bl[nb][0] = Bl[o];
                bl[nb][1] = Bl[o + 4];
            }
            #pragma unroll
            for (int mb = 0; mb < 2; mb++)
                #pragma unroll
                for (int nb = 0; nb < 8; nb++) {
                    MMA_TF32(acc[mb][nb], ah[mb], bh[nb]);
                    MMA_TF32(acc[mb][nb], ah[mb], bl[nb]);
                    MMA_TF32(acc[mb][nb], al[mb], bh[nb]);
                }
        }
        __syncthreads();
    }

    // epilogue: logits + row max
    float rmax[4] = {-3e38f, -3e38f, -3e38f, -3e38f};
    #pragma unroll
    for (int mb = 0; mb < 2; mb++) {
        int r0 = wm * 32 + mb * 16 + gr, r1 = r0 + 8;
        float inv0 = sInvd[r0], inv1 = sInvd[r1];
        #pragma unroll
        for (int nb = 0; nb < 8; nb++) {
            int n0 = wn * 64 + nb * 8 + 2 * lc;
            float s20 = sS2[n0], s21 = sS2[n0 + 1];
            float l00 = (acc[mb][nb][0] - s20) * inv0;
            float l01 = (acc[mb][nb][1] - s21) * inv0;
            float l10 = (acc[mb][nb][2] - s20) * inv1;
            float l11 = (acc[mb][nb][3] - s21) * inv1;
            *(float2*)&g_S[(long long)(qbase + r0) * NS + nbase + n0] =
                make_float2(l00, l01);
            *(float2*)&g_S[(long long)(qbase + r1) * NS + nbase + n0] =
                make_float2(l10, l11);
            rmax[2 * mb] = fmaxf(rmax[2 * mb], fmaxf(l00, l01));
            rmax[2 * mb + 1] = fmaxf(rmax[2 * mb + 1], fmaxf(l10, l11));
        }
    }
    #pragma unroll
    for (int i = 0; i < 4; i++) {
        rmax[i] = fmaxf(rmax[i], __shfl_xor_sync(0xffffffffu, rmax[i], 1));
        rmax[i] = fmaxf(rmax[i], __shfl_xor_sync(0xffffffffu, rmax[i], 2));
    }
    if (lc == 0) {
        #pragma unroll
        for (int mb = 0; mb < 2; mb++) {
            int r0 = wm * 32 + mb * 16 + gr;
            atomicMax(&g_mU[qbase + r0], fmap(rmax[2 * mb]));
            atomicMax(&g_mU[qbase + r0 + 8], fmap(rmax[2 * mb + 1]));
        }
    }
}

// ---------------- softmax rows of g_S in place (P = tf32-rounded) ----------
__global__ __launch_bounds__(256) void softmax_kernel() {
    int q = blockIdx.x;
    int tid = threadIdx.x;
    unsigned mu = g_mU[q];
    float m = (mu & 0x80000000u) ? __uint_as_float(mu ^ 0x80000000u)
                                 : __uint_as_float(~mu);
    float4* row = (float4*)(g_S + (long long)q * NS);
    float sum = 0.f;
    #pragma unroll
    for (int i = tid; i < NS / 4; i += 256) {
        float4 v = row[i];
        v.x = to_tf32(__expf(v.x - m));
        v.y = to_tf32(__expf(v.y - m));
        v.z = to_tf32(__expf(v.z - m));
        v.w = to_tf32(__expf(v.w - m));
        sum += (v.x + v.y) + (v.z + v.w);
        row[i] = v;
    }
    #pragma unroll
    for (int o = 16; o; o >>= 1) sum += __shfl_xor_sync(0xffffffffu, sum, o);
    __shared__ float red[8];
    if ((tid & 31) == 0) red[tid >> 5] = sum;
    __syncthreads();
    if (tid == 0) {
        float t = 0.f;
        #pragma unroll
        for (int i = 0; i < 8; i++) t += red[i];
        g_l[q] = t;
    }
}

// ---------------- GEMM2: O_part = P @ samples (tf32 2-product, split-K) ----
// CTA tile: 128 q x 128 d, K = 2048 samples in 64 chunks of 32.
#define G2_BUF (3 * TILE_F)                // P, Bh, Bl
#define G2_SMEM (2 * G2_BUF * 4)

static __device__ __forceinline__ void g2_load(int tid, float* buf, int qbase,
                                               int dbase, int kb) {
    u32 b = smem_u32(buf);
    #pragma unroll
    for (int it = 0; it < 12; it++) {
        int i = tid + it * 256;
        int sec = i >> 10, j = i & 1023;
        int row = j >> 3, c = (j & 7) * 4;
        const float* src;
        if (sec == 0)      src = g_S + (long long)(qbase + row) * NS + kb + c;
        else if (sec == 1) src = g_ST + (long long)(dbase + row) * NS + kb + c;
        else               src = g_STl + (long long)(dbase + row) * NS + kb + c;
        CP_ASYNC16(b + (u32)((sec * TILE_F + row * KCP + c) * 4), src);
    }
}

__global__ __launch_bounds__(256, 1) void gemm2_kernel() {
    extern __shared__ float sm[];
    const int tid = threadIdx.x;
    const int qt = blockIdx.x >> 3;
    const int dt = (blockIdx.x >> 2) & 1;
    const int sp = blockIdx.x & 3;
    const int qbase = qt * 128, dbase = dt * 128, kb0 = sp * KSP;

    g2_load(tid, sm, qbase, dbase, kb0);
    CP_COMMIT();

    const int wid = tid >> 5, lane = tid & 31;
    const int wm = wid >> 1, wn = wid & 1;
    const int gr = lane >> 2, lc = lane & 3;

    float acc[2][8][4];
    #pragma unroll
    for (int mb = 0; mb < 2; mb++)
        #pragma unroll
        for (int nb = 0; nb < 8; nb++)
            #pragma unroll
            for (int e = 0; e < 4; e++) acc[mb][nb][e] = 0.f;

    for (int s = 0; s < KSP / 32; s++) {
        float* buf = sm + (s & 1) * G2_BUF;
        if (s + 1 < KSP / 32) {
            g2_load(tid, sm + ((s + 1) & 1) * G2_BUF, qbase, dbase,
                    kb0 + (s + 1) * 32);
            CP_COMMIT();
            CP_WAIT1();
        } else {
            CP_WAIT0();
        }
        __syncthreads();
        const float* P = buf;
        const float* Bh = buf + TILE_F;
        const float* Bl = buf + 2 * TILE_F;
        #pragma unroll
        for (int ks = 0; ks < 4; ks++) {
            int k0 = ks * 8;
            float a[2][4];
            #pragma unroll
            for (int mb = 0; mb < 2; mb++) {
                int o0 = (wm * 32 + mb * 16 + gr) * KCP + k0 + lc;
                a[mb][0] = P[o0];       a[mb][1] = P[o0 + 8 * KCP];
                a[mb][2] = P[o0 + 4];   a[mb][3] = P[o0 + 8 * KCP + 4];
            }
            float bh[8][2], bl[8][2];
            #pragma unroll
            for (int nb = 0; nb < 8; nb++) {
                int o = (wn * 64 + nb * 8 + gr) * KCP + k0 + lc;
                bh[nb][0] = Bh[o];
                bh[nb][1] = Bh[o + 4];
                bl[nb][0] = Bl[o];
                bl[nb][1] = Bl[o + 4];
            }
            #pragma unroll
            for (int mb = 0; mb < 2; mb++)
                #pragma unroll
                for (int nb = 0; nb < 8; nb++) {
                    MMA_TF32(acc[mb][nb], a[mb], bh[nb]);
                    MMA_TF32(acc[mb][nb], a[mb], bl[nb]);
                }
        }
        __syncthreads();
    }

    // epilogue: store unnormalized O partials
    #pragma unroll
    for (int mb = 0; mb < 2; mb++) {
        int r0 = wm * 32 + mb * 16 + gr, r1 = r0 + 8;
        #pragma unroll
        for (int nb = 0; nb < 8; nb++) {
            int n0 = dbase + wn * 64 + nb * 8 + 2 * lc;
            *(float2*)&g_Op[sp][(qbase + r0) * DD + n0] =
                make_float2(acc[mb][nb][0], acc[mb][nb][1]);
            *(float2*)&g_Op[sp][(qbase + r1) * DD + n0] =
                make_float2(acc[mb][nb][2], acc[mb][nb][3]);
        }
    }
}

// ---------------- combine ----------------
__global__ void combine_kernel(const float* __restrict__ tvec,
                               const float* __restrict__ x,
                               float* __restrict__ out) {
    int idx = blockIdx.x * 256 + threadIdx.x;  // BQ * 64
    int q = idx >> 6, c4 = idx & 63;
    float linv = 1.0f / g_l[q];
    float tt = tvec[q];
    float ts = 0.01f * exp2f(tt * 13.287712379549449f);
    float scale = ts / fmaf(ts, ts, 1e-8f);
    float4 a = make_float4(0.f, 0.f, 0.f, 0.f);
    #pragma unroll
    for (int sp = 0; sp < NSPLIT; sp++) {
        float4 v = *(const float4*)(g_Op[sp] + q * DD + c4 * 4);
        a.x += v.x;
        a.y += v.y;
        a.z += v.z;
        a.w += v.w;
    }
    float4 xx = *(const float4*)(x + (long long)q * DD + c4 * 4);
    float4 r;
    r.x = (a.x * linv - xx.x) * scale;
    r.y = (a.y * linv - xx.y) * scale;
    r.z = (a.z * linv - xx.z) * scale;
    r.w = (a.w * linv - xx.w) * scale;
    *(float4*)(out + (long long)q * DD + c4 * 4) = r;
}

extern "C" void kernel_launch(void* const* d_in, const int* in_sizes, int n_in,
                              void* d_out, int out_size) {
    const float* t = nullptr;
    const float* x = nullptr;
    const float* s = nullptr;
    for (int i = 0; i < n_in; i++) {
        if (in_sizes[i] == BQ) t = (const float*)d_in[i];
        else if (in_sizes[i] == BQ * DD) x = (const float*)d_in[i];
        else if (in_sizes[i] == NS * DD) s = (const float*)d_in[i];
    }
    float* out = (float*)d_out;

    init_kernel<<<BQ / 256, 256>>>(t);
    split_x_kernel<<<BQ * DD / 256, 256>>>(x);
    split_s_kernel<<<NS * DD / 256, 256>>>(s);
    transpose_kernel<<<dim3(NS / 32, DD / 32), dim3(32, 8)>>>(s);
    s2_kernel<<<NS / 8, 256>>>(s);

    cudaFuncSetAttribute(gemm1_kernel, cudaFuncAttributeMaxDynamicSharedMemorySize,
                         G1_SMEM);
    gemm1_kernel<<<(BQ / 128) * (NS / 128), 256, G1_SMEM>>>();

    softmax_kernel<<<BQ, 256>>>();

    cudaFuncSetAttribute(gemm2_kernel, cudaFuncAttributeMaxDynamicSharedMemorySize,
                         G2_SMEM);
    gemm2_kernel<<<(BQ / 128) * 2 * NSPLIT, 256, G2_SMEM>>>();

    combine_kernel<<<BQ * 64 / 256, 256>>>(t, x, out);
}

// round 13
// speedup vs baseline: 2.0643x; 1.3316x over previous
#include <cuda_runtime.h>
#include <cuda_bf16.h>

typedef unsigned int u32;
typedef unsigned long long u64;

#define BQ 4096
#define NS 8192
#define DD 256
#define NSPLIT 4
#define KSP (NS / NSPLIT)   // 2048 samples per split-K CTA

// ---------------- static scratch ----------------
__device__ __nv_bfloat16 g_Xh[BQ * DD];
__device__ __nv_bfloat16 g_Xl[BQ * DD];
__device__ __nv_bfloat16 g_Sh[NS * DD];
__device__ __nv_bfloat16 g_Sl[NS * DD];
__device__ float g_ST[DD * NS];    // transposed samples, tf32-rounded (high)
__device__ float g_STl[DD * NS];   // transposed samples residual (tf32-rounded)
__device__ float g_s2half[NS];
__device__ float g_invd[BQ];
__device__ unsigned g_mU[BQ];      // monotone-mapped row max
__device__ float g_l[BQ];
__device__ float g_S[(long long)BQ * NS];   // logits, then P (in place)
__device__ float g_Op[NSPLIT][BQ * DD];

// ---------------- helpers ----------------
static __device__ __forceinline__ u32 smem_u32(const void* p) {
    return (u32)__cvta_generic_to_shared(p);
}
static __device__ __forceinline__ float to_tf32(float v) {
    float r;
    asm("cvt.rna.tf32.f32 %0, %1;" : "=f"(r) : "f"(v));
    return r;
}
static __device__ __forceinline__ unsigned fmap(float v) {
    unsigned u = __float_as_uint(v);
    return (u & 0x80000000u) ? ~u : (u | 0x80000000u);
}

#define CP_ASYNC16(dst_u32, src_ptr)                                         \
    asm volatile("cp.async.cg.shared.global [%0], [%1], 16;" ::"r"(dst_u32), \
                 "l"(src_ptr))
#define CP_COMMIT() asm volatile("cp.async.commit_group;" ::: "memory")
#define CP_WAIT1() asm volatile("cp.async.wait_group 1;" ::: "memory")
#define CP_WAIT0() asm volatile("cp.async.wait_group 0;" ::: "memory")

// m16n8k8 tf32 mma: D += A*B  (A row-major m16k8, B col-major k8n8)
#define MMA_TF32(d, a, b)                                                   \
    asm volatile(                                                           \
        "mma.sync.aligned.m16n8k8.row.col.f32.tf32.tf32.f32 "               \
        "{%0,%1,%2,%3}, {%4,%5,%6,%7}, {%8,%9}, {%0,%1,%2,%3};"             \
        : "+f"((d)[0]), "+f"((d)[1]), "+f"((d)[2]), "+f"((d)[3])            \
        : "r"(__float_as_uint((a)[0])), "r"(__float_as_uint((a)[1])),       \
          "r"(__float_as_uint((a)[2])), "r"(__float_as_uint((a)[3])),       \
          "r"(__float_as_uint((b)[0])), "r"(__float_as_uint((b)[1])))

// m16n8k16 bf16 mma: D += A*B (A row-major m16k16, B col-major k16n8)
#define MMA_BF16(d, a, b)                                                   \
    asm volatile(                                                           \
        "mma.sync.aligned.m16n8k16.row.col.f32.bf16.bf16.f32 "              \
        "{%0,%1,%2,%3}, {%4,%5,%6,%7}, {%8,%9}, {%0,%1,%2,%3};"             \
        : "+f"((d)[0]), "+f"((d)[1]), "+f"((d)[2]), "+f"((d)[3])            \
        : "r"((a)[0]), "r"((a)[1]), "r"((a)[2]), "r"((a)[3]),               \
          "r"((b)[0]), "r"((b)[1]))

// fp32 tiles: padded row stride 36 words: (36r + c) mod 32 = (4r + c) mod 32
#define KCP 36
#define TILE_F (128 * TILE stride? ) /* placeholder removed below */
#undef TILE_F
#define TILE_F (128 * KCP)  // 4608 floats per 128x32 fp32 tile

// bf16 tiles (gemm1): 32 bf16 per row = 16 words, padded stride 20 words:
// (20r + c) mod 32 over r=0..7, c=0..3 covers all 32 banks -> conflict-free.
#define G1W 20
#define G1TILE (128 * G1W)       // 2560 words per tile
#define G1BUF (4 * G1TILE)       // Ah, Al, Bh, Bl = 10240 words
#define G1_SMEM ((2 * G1BUF + 256) * 4)

// ---------------- prep kernels ----------------
__global__ void init_kernel(const float* __restrict__ tvec) {
    int q = blockIdx.x * 256 + threadIdx.x;
    float tt = tvec[q];
    float ts = 0.01f * exp2f(tt * 13.287712379549449f);
    g_invd[q] = 1.0f / fmaf(ts, ts, 1e-8f);
    g_mU[q] = 0u;
}

__global__ void split_x_kernel(const float* __restrict__ x) {
    int i = blockIdx.x * 256 + threadIdx.x;
    float v = x[i];
    __nv_bfloat16 h = __float2bfloat16(v);
    g_Xh[i] = h;
    g_Xl[i] = __float2bfloat16(v - __bfloat162float(h));
}

// samples: bf16 split (row-major, gemm1) + tf32 split transpose (gemm2)
__global__ void transpose_kernel(const float* __restrict__ s) {
    __shared__ float T[32][33];
    int s0 = blockIdx.x * 32, d0 = blockIdx.y * 32;
    int tx = threadIdx.x, ty = threadIdx.y;  // (32, 8)
    #pragma unroll
    for (int j = 0; j < 32; j += 8) {
        long long idx = (long long)(s0 + ty + j) * DD + d0 + tx;
        float v = s[idx];
        T[ty + j][tx] = v;
        __nv_bfloat16 h = __float2bfloat16(v);
        g_Sh[idx] = h;
        g_Sl[idx] = __float2bfloat16(v - __bfloat162float(h));
    }
    __syncthreads();
    #pragma unroll
    for (int j = 0; j < 32; j += 8) {
        float v = T[tx][ty + j];
        float h = to_tf32(v);
        long long o = (long long)(d0 + ty + j) * NS + s0 + tx;
        g_ST[o] = h;
        g_STl[o] = to_tf32(v - h);
    }
}

__global__ void s2_kernel(const float* __restrict__ samples) {
    int w = (blockIdx.x * blockDim.x + threadIdx.x) >> 5;
    int lane = threadIdx.x & 31;
    if (w >= NS) return;
    const float* row = samples + (size_t)w * DD;
    float s = 0.f;
    #pragma unroll
    for (int i = 0; i < DD / 32; i++) {
        float v = row[lane + 32 * i];
        s = fmaf(v, v, s);
    }
    #pragma unroll
    for (int o = 16; o; o >>= 1) s += __shfl_xor_sync(0xffffffffu, s, o);
    if (lane == 0) g_s2half[w] = 0.5f * s;
}

// ---------------- GEMM1: logits = (X @ S^T - s2half) * invd ----------------
// CTA tile: 128 q x 128 n, K=256 in 8 chunks of 32, bf16 3-product split.
static __device__ __forceinline__ void g1_load(int tid, u32 b, int qbase,
                                               int nbase, int kb) {
    #pragma unroll
    for (int it = 0; it < 8; it++) {
        int i = tid + it * 256;
        int sec = i >> 9, j = i & 511;
        int row = j >> 2, c = j & 3;   // c = 16B chunk (8 bf16)
        const __nv_bfloat16* src;
        if (sec == 0)      src = g_Xh + (size_t)(qbase + row) * DD + kb + 8 * c;
        else if (sec == 1) src = g_Xl + (size_t)(qbase + row) * DD + kb + 8 * c;
        else if (sec == 2) src = g_Sh + (size_t)(nbase + row) * DD + kb + 8 * c;
        else               src = g_Sl + (size_t)(nbase + row) * DD + kb + 8 * c;
        CP_ASYNC16(b + (u32)((sec * G1TILE + row * G1W + c * 4) * 4), src);
    }
}

__global__ __launch_bounds__(256, 2) void gemm1_kernel() {
    extern __shared__ float sm[];
    float* sInvd = sm + 2 * G1BUF;
    float* sS2 = sInvd + 128;
    const int tid = threadIdx.x;
    const int qt = blockIdx.x >> 6, nt = blockIdx.x & 63;
    const int qbase = qt * 128, nbase = nt * 128;
    const u32 sb = smem_u32(sm);

    if (tid < 128) {
        sInvd[tid] = g_invd[qbase + tid];
        sS2[tid] = g_s2half[nbase + tid];
    }
    g1_load(tid, sb, qbase, nbase, 0);
    CP_COMMIT();

    const int wid = tid >> 5, lane = tid & 31;
    const int wm = wid >> 1, wn = wid & 1;
    const int gr = lane >> 2, lc = lane & 3;

    float acc[2][8][4];
    #pragma unroll
    for (int mb = 0; mb < 2; mb++)
        #pragma unroll
        for (int nb = 0; nb < 8; nb++)
            #pragma unroll
            for (int e = 0; e < 4; e++) acc[mb][nb][e] = 0.f;

    for (int s = 0; s < 8; s++) {
        const u32* buf = (const u32*)sm + (s & 1) * G1BUF;
        if (s + 1 < 8) {
            g1_load(tid, sb + (u32)(((s + 1) & 1) * G1BUF * 4), qbase, nbase,
                    (s + 1) * 32);
            CP_COMMIT();
            CP_WAIT1();
        } else {
            CP_WAIT0();
        }
        __syncthreads();
        const u32* Ah = buf;
        const u32* Al = buf + G1TILE;
        const u32* Bh = buf + 2 * G1TILE;
        const u32* Bl = buf + 3 * G1TILE;
        #pragma unroll
        for (int ks = 0; ks < 2; ks++) {
            int k0w = ks * 8;
            u32 ah[2][4], al[2][4];
            #pragma unroll
            for (int mb = 0; mb < 2; mb++) {
                int o0 = (wm * 32 + mb * 16 + gr) * G1W + k0w + lc;
                ah[mb][0] = Ah[o0];              ah[mb][1] = Ah[o0 + 8 * G1W];
                ah[mb][2] = Ah[o0 + 4];          ah[mb][3] = Ah[o0 + 8 * G1W + 4];
                al[mb][0] = Al[o0];              al[mb][1] = Al[o0 + 8 * G1W];
                al[mb][2] = Al[o0 + 4];          al[mb][3] = Al[o0 + 8 * G1W + 4];
            }
            u32 bh[8][2], bl[8][2];
            #pragma unroll
            for (int nb = 0; nb < 8; nb++) {
                int o = (wn * 64 + nb * 8 + gr) * G1W + k0w + lc;
                bh[nb][0] = Bh[o];
                bh[nb][1] = Bh[o + 4];
                bl[nb][0] = Bl[o];
                bl[nb][1] = Bl[o + 4];
            }
            #pragma unroll
            for (int mb = 0; mb < 2; mb++)
                #pragma unroll
                for (int nb = 0; nb < 8; nb++) {
                    MMA_BF16(acc[mb][nb], ah[mb], bh[nb]);
                    MMA_BF16(acc[mb][nb], ah[mb], bl[nb]);
                    MMA_BF16(acc[mb][nb], al[mb], bh[nb]);
                }
        }
        __syncthreads();
    }

    // epilogue: logits + row max
    float rmax[4] = {-3e38f, -3e38f, -3e38f, -3e38f};
    #pragma unroll
    for (int mb = 0; mb < 2; mb++) {
        int r0 = wm * 32 + mb * 16 + gr, r1 = r0 + 8;
        float inv0 = sInvd[r0], inv1 = sInvd[r1];
        #pragma unroll
        for (int nb = 0; nb < 8; nb++) {
            int n0 = wn * 64 + nb * 8 + 2 * lc;
            float s20 = sS2[n0], s21 = sS2[n0 + 1];
            float l00 = (acc[mb][nb][0] - s20) * inv0;
            float l01 = (acc[mb][nb][1] - s21) * inv0;
            float l10 = (acc[mb][nb][2] - s20) * inv1;
            float l11 = (acc[mb][nb][3] - s21) * inv1;
            *(float2*)&g_S[(long long)(qbase + r0) * NS + nbase + n0] =
                make_float2(l00, l01);
            *(float2*)&g_S[(long long)(qbase + r1) * NS + nbase + n0] =
                make_float2(l10, l11);
            rmax[2 * mb] = fmaxf(rmax[2 * mb], fmaxf(l00, l01));
            rmax[2 * mb + 1] = fmaxf(rmax[2 * mb + 1], fmaxf(l10, l11));
        }
    }
    #pragma unroll
    for (int i = 0; i < 4; i++) {
        rmax[i] = fmaxf(rmax[i], __shfl_xor_sync(0xffffffffu, rmax[i], 1));
        rmax[i] = fmaxf(rmax[i], __shfl_xor_sync(0xffffffffu, rmax[i], 2));
    }
    if (lc == 0) {
        #pragma unroll
        for (int mb = 0; mb < 2; mb++) {
            int r0 = wm * 32 + mb * 16 + gr;
            atomicMax(&g_mU[qbase + r0], fmap(rmax[2 * mb]));
            atomicMax(&g_mU[qbase + r0 + 8], fmap(rmax[2 * mb + 1]));
        }
    }
}

// ---------------- softmax rows of g_S in place (P = tf32-rounded) ----------
__global__ __launch_bounds__(256) void softmax_kernel() {
    int q = blockIdx.x;
    int tid = threadIdx.x;
    unsigned mu = g_mU[q];
    float m = (mu & 0x80000000u) ? __uint_as_float(mu ^ 0x80000000u)
                                 : __uint_as_float(~mu);
    float4* row = (float4*)(g_S + (long long)q * NS);
    float sum = 0.f;
    #pragma unroll
    for (int i = tid; i < NS / 4; i += 256) {
        float4 v = row[i];
        v.x = to_tf32(__expf(v.x - m));
        v.y = to_tf32(__expf(v.y - m));
        v.z = to_tf32(__expf(v.z - m));
        v.w = to_tf32(__expf(v.w - m));
        sum += (v.x + v.y) + (v.z + v.w);
        row[i] = v;
    }
    #pragma unroll
    for (int o = 16; o; o >>= 1) sum += __shfl_xor_sync(0xffffffffu, sum, o);
    __shared__ float red[8];
    if ((tid & 31) == 0) red[tid >> 5] = sum;
    __syncthreads();
    if (tid == 0) {
        float t = 0.f;
        #pragma unroll
        for (int i = 0; i < 8; i++) t += red[i];
        g_l[q] = t;
    }
}

// ---------------- GEMM2: O_part = P @ samples (tf32 2-product, split-K) ----
// CTA tile: 128 q x 128 d, K = 2048 samples in 64 chunks of 32.
#define G2_BUF (3 * TILE_F)                // P, Bh, Bl
#define G2_SMEM (2 * G2_BUF * 4)

static __device__ __forceinline__ void g2_load(int tid, float* buf, int qbase,
                                               int dbase, int kb) {
    u32 b = smem_u32(buf);
    #pragma unroll
    for (int it = 0; it < 12; it++) {
        int i = tid + it * 256;
        int sec = i >> 10, j = i & 1023;
        int row = j >> 3, c = (j & 7) * 4;
        const float* src;
        if (sec == 0)      src = g_S + (long long)(qbase + row) * NS + kb + c;
        else if (sec == 1) src = g_ST + (long long)(dbase + row) * NS + kb + c;
        else               src = g_STl + (long long)(dbase + row) * NS + kb + c;
        CP_ASYNC16(b + (u32)((sec * TILE_F + row * KCP + c) * 4), src);
    }
}

__global__ __launch_bounds__(256, 1) void gemm2_kernel() {
    extern __shared__ float sm[];
    const int tid = threadIdx.x;
    const int qt = blockIdx.x >> 3;
    const int dt = (blockIdx.x >> 2) & 1;
    const int sp = blockIdx.x & 3;
    const int qbase = qt * 128, dbase = dt * 128, kb0 = sp * KSP;

    g2_load(tid, sm, qbase, dbase, kb0);
    CP_COMMIT();

    const int wid = tid >> 5, lane = tid & 31;
    const int wm = wid >> 1, wn = wid & 1;
    const int gr = lane >> 2, lc = lane & 3;

    float acc[2][8][4];
    #pragma unroll
    for (int mb = 0; mb < 2; mb++)
        #pragma unroll
        for (int nb = 0; nb < 8; nb++)
            #pragma unroll
            for (int e = 0; e < 4; e++) acc[mb][nb][e] = 0.f;

    for (int s = 0; s < KSP / 32; s++) {
        float* buf = sm + (s & 1) * G2_BUF;
        if (s + 1 < KSP / 32) {
            g2_load(tid, sm + ((s + 1) & 1) * G2_BUF, qbase, dbase,
                    kb0 + (s + 1) * 32);
            CP_COMMIT();
            CP_WAIT1();
        } else {
            CP_WAIT0();
        }
        __syncthreads();
        const float* P = buf;
        const float* Bh = buf + TILE_F;
        const float* Bl = buf + 2 * TILE_F;
        #pragma unroll
        for (int ks = 0; ks < 4; ks++) {
            int k0 = ks * 8;
            float a[2][4];
            #pragma unroll
            for (int mb = 0; mb < 2; mb++) {
                int o0 = (wm * 32 + mb * 16 + gr) * KCP + k0 + lc;
                a[mb][0] = P[o0];       a[mb][1] = P[o0 + 8 * KCP];
                a[mb][2] = P[o0 + 4];   a[mb][3] = P[o0 + 8 * KCP + 4];
            }
            float bh[8][2], bl[8][2];
            #pragma unroll
            for (int nb = 0; nb < 8; nb++) {
                int o = (wn * 64 + nb * 8 + gr) * KCP + k0 + lc;
                bh[nb][0] = Bh[o];
                bh[nb][1] = Bh[o + 4];
                bl[nb][0] = Bl[o];
                bl[nb][1] = Bl[o + 4];
            }
            #pragma unroll
            for (int mb = 0; mb < 2; mb++)
                #pragma unroll
                for (int nb = 0; nb < 8; nb++) {
                    MMA_TF32(acc[mb][nb], a[mb], bh[nb]);
                    MMA_TF32(acc[mb][nb], a[mb], bl[nb]);
                }
        }
        __syncthreads();
    }

    // epilogue: store unnormalized O partials
    #pragma unroll
    for (int mb = 0; mb < 2; mb++) {
        int r0 = wm * 32 + mb * 16 + gr, r1 = r0 + 8;
        #pragma unroll
        for (int nb = 0; nb < 8; nb++) {
            int n0 = dbase + wn * 64 + nb * 8 + 2 * lc;
            *(float2*)&g_Op[sp][(qbase + r0) * DD + n0] =
                make_float2(acc[mb][nb][0], acc[mb][nb][1]);
            *(float2*)&g_Op[sp][(qbase + r1) * DD + n0] =
                make_float2(acc[mb][nb][2], acc[mb][nb][3]);
        }
    }
}

// ---------------- combine ----------------
__global__ void combine_kernel(const float* __restrict__ tvec,
                               const float* __restrict__ x,
                               float* __restrict__ out) {
    int idx = blockIdx.x * 256 + threadIdx.x;  // BQ * 64
    int q = idx >> 6, c4 = idx & 63;
    float linv = 1.0f / g_l[q];
    float tt = tvec[q];
    float ts = 0.01f * exp2f(tt * 13.287712379549449f);
    float scale = ts / fmaf(ts, ts, 1e-8f);
    float4 a = make_float4(0.f, 0.f, 0.f, 0.f);
    #pragma unroll
    for (int sp = 0; sp < NSPLIT; sp++) {
        float4 v = *(const float4*)(g_Op[sp] + q * DD + c4 * 4);
        a.x += v.x;
        a.y += v.y;
        a.z += v.z;
        a.w += v.w;
    }
    float4 xx = *(const float4*)(x + (long long)q * DD + c4 * 4);
    float4 r;
    r.x = (a.x * linv - xx.x) * scale;
    r.y = (a.y * linv - xx.y) * scale;
    r.z = (a.z * linv - xx.z) * scale;
    r.w = (a.w * linv - xx.w) * scale;
    *(float4*)(out + (long long)q * DD + c4 * 4) = r;
}

extern "C" void kernel_launch(void* const* d_in, const int* in_sizes, int n_in,
                              void* d_out, int out_size) {
    const float* t = nullptr;
    const float* x = nullptr;
    const float* s = nullptr;
    for (int i = 0; i < n_in; i++) {
        if (in_sizes[i] == BQ) t = (const float*)d_in[i];
        else if (in_sizes[i] == BQ * DD) x = (const float*)d_in[i];
        else if (in_sizes[i] == NS * DD) s = (const float*)d_in[i];
    }
    float* out = (float*)d_out;

    init_kernel<<<BQ / 256, 256>>>(t);
    split_x_kernel<<<BQ * DD / 256, 256>>>(x);
    transpose_kernel<<<dim3(NS / 32, DD / 32), dim3(32, 8)>>>(s);
    s2_kernel<<<NS / 8, 256>>>(s);

    cudaFuncSetAttribute(gemm1_kernel, cudaFuncAttributeMaxDynamicSharedMemorySize,
                         G1_SMEM);
    gemm1_kernel<<<(BQ / 128) * (NS / 128), 256, G1_SMEM>>>();

    softmax_kernel<<<BQ, 256>>>();

    cudaFuncSetAttribute(gemm2_kernel, cudaFuncAttributeMaxDynamicSharedMemorySize,
                         G2_SMEM);
    gemm2_kernel<<<(BQ / 128) * 2 * NSPLIT, 256, G2_SMEM>>>();

    combine_kernel<<<BQ * 64 / 256, 256>>>(t, x, out);
}

// round 14
// speedup vs baseline: 2.2527x; 1.0913x over previous
#include <cuda_runtime.h>
#include <cuda_bf16.h>

typedef unsigned int u32;
typedef unsigned long long u64;

#define BQ 4096
#define NS 8192
#define DD 256
#define NSPLIT 4
#define KSP (NS / NSPLIT)   // 2048 samples per split-K CTA

// ---------------- static scratch ----------------
__device__ __nv_bfloat16 g_Xh[BQ * DD];
__device__ __nv_bfloat16 g_Xl[BQ * DD];
__device__ __nv_bfloat16 g_Sh[NS * DD];
__device__ __nv_bfloat16 g_Sl[NS * DD];
__device__ __nv_bfloat16 g_STh[DD * NS];   // transposed samples bf16 high
__device__ __nv_bfloat16 g_STl[DD * NS];   // transposed samples bf16 low
__device__ __nv_bfloat16 g_Ph[(long long)BQ * NS];  // P bf16 high
__device__ __nv_bfloat16 g_Pl[(long long)BQ * NS];  // P bf16 low
__device__ float g_s2half[NS];
__device__ float g_invd[BQ];
__device__ unsigned g_mU[BQ];      // monotone-mapped row max
__device__ float g_l[BQ];
__device__ float g_S[(long long)BQ * NS];   // logits
__device__ float g_Op[NSPLIT][BQ * DD];

// ---------------- helpers ----------------
static __device__ __forceinline__ u32 smem_u32(const void* p) {
    return (u32)__cvta_generic_to_shared(p);
}
static __device__ __forceinline__ unsigned fmap(float v) {
    unsigned u = __float_as_uint(v);
    return (u & 0x80000000u) ? ~u : (u | 0x80000000u);
}

#define CP_ASYNC16(dst_u32, src_ptr)                                         \
    asm volatile("cp.async.cg.shared.global [%0], [%1], 16;" ::"r"(dst_u32), \
                 "l"(src_ptr))
#define CP_COMMIT() asm volatile("cp.async.commit_group;" ::: "memory")
#define CP_WAIT1() asm volatile("cp.async.wait_group 1;" ::: "memory")
#define CP_WAIT0() asm volatile("cp.async.wait_group 0;" ::: "memory")

// m16n8k16 bf16 mma: D += A*B (A row-major m16k16, B col-major k16n8)
#define MMA_BF16(d, a, b)                                                   \
    asm volatile(                                                           \
        "mma.sync.aligned.m16n8k16.row.col.f32.bf16.bf16.f32 "              \
        "{%0,%1,%2,%3}, {%4,%5,%6,%7}, {%8,%9}, {%0,%1,%2,%3};"             \
        : "+f"((d)[0]), "+f"((d)[1]), "+f"((d)[2]), "+f"((d)[3])            \
        : "r"((a)[0]), "r"((a)[1]), "r"((a)[2]), "r"((a)[3]),               \
          "r"((b)[0]), "r"((b)[1]))

// bf16 tiles: 32 bf16 per row = 16 words, padded stride 20 words:
// (20r + c) mod 32 over r=0..7, c=0..3 covers all 32 banks -> conflict-free.
#define G1W 20
#define G1TILE (128 * G1W)       // 2560 words per 128x32 bf16 tile
#define G1BUF (4 * G1TILE)       // 4 tiles = 10240 words
#define G1_SMEM ((2 * G1BUF + 256) * 4)
#define G2_SMEM (2 * G1BUF * 4)

// ---------------- prep kernels ----------------
__global__ void init_kernel(const float* __restrict__ tvec) {
    int q = blockIdx.x * 256 + threadIdx.x;
    float tt = tvec[q];
    float ts = 0.01f * exp2f(tt * 13.287712379549449f);
    g_invd[q] = 1.0f / fmaf(ts, ts, 1e-8f);
    g_mU[q] = 0u;
}

__global__ void split_x_kernel(const float* __restrict__ x) {
    int i = blockIdx.x * 256 + threadIdx.x;
    float v = x[i];
    __nv_bfloat16 h = __float2bfloat16(v);
    g_Xh[i] = h;
    g_Xl[i] = __float2bfloat16(v - __bfloat162float(h));
}

// samples: bf16 split row-major (gemm1) + bf16 split transposed (gemm2)
__global__ void transpose_kernel(const float* __restrict__ s) {
    __shared__ float T[32][33];
    int s0 = blockIdx.x * 32, d0 = blockIdx.y * 32;
    int tx = threadIdx.x, ty = threadIdx.y;  // (32, 8)
    #pragma unroll
    for (int j = 0; j < 32; j += 8) {
        long long idx = (long long)(s0 + ty + j) * DD + d0 + tx;
        float v = s[idx];
        T[ty + j][tx] = v;
        __nv_bfloat16 h = __float2bfloat16(v);
        g_Sh[idx] = h;
        g_Sl[idx] = __float2bfloat16(v - __bfloat162float(h));
    }
    __syncthreads();
    #pragma unroll
    for (int j = 0; j < 32; j += 8) {
        float v = T[tx][ty + j];
        long long o = (long long)(d0 + ty + j) * NS + s0 + tx;
        __nv_bfloat16 h = __float2bfloat16(v);
        g_STh[o] = h;
        g_STl[o] = __float2bfloat16(v - __bfloat162float(h));
    }
}

__global__ void s2_kernel(const float* __restrict__ samples) {
    int w = (blockIdx.x * blockDim.x + threadIdx.x) >> 5;
    int lane = threadIdx.x & 31;
    if (w >= NS) return;
    const float* row = samples + (size_t)w * DD;
    float s = 0.f;
    #pragma unroll
    for (int i = 0; i < DD / 32; i++) {
        float v = row[lane + 32 * i];
        s = fmaf(v, v, s);
    }
    #pragma unroll
    for (int o = 16; o; o >>= 1) s += __shfl_xor_sync(0xffffffffu, s, o);
    if (lane == 0) g_s2half[w] = 0.5f * s;
}

// ---------------- GEMM1: logits = (X @ S^T - s2half) * invd ----------------
// CTA tile: 128 q x 128 n, K=256 in 8 chunks of 32, bf16 3-product split.
static __device__ __forceinline__ void g1_load(int tid, u32 b, int qbase,
                                               int nbase, int kb) {
    #pragma unroll
    for (int it = 0; it < 8; it++) {
        int i = tid + it * 256;
        int sec = i >> 9, j = i & 511;
        int row = j >> 2, c = j & 3;   // c = 16B chunk (8 bf16)
        const __nv_bfloat16* src;
        if (sec == 0)      src = g_Xh + (size_t)(qbase + row) * DD + kb + 8 * c;
        else if (sec == 1) src = g_Xl + (size_t)(qbase + row) * DD + kb + 8 * c;
        else if (sec == 2) src = g_Sh + (size_t)(nbase + row) * DD + kb + 8 * c;
        else               src = g_Sl + (size_t)(nbase + row) * DD + kb + 8 * c;
        CP_ASYNC16(b + (u32)((sec * G1TILE + row * G1W + c * 4) * 4), src);
    }
}

__global__ __launch_bounds__(256, 2) void gemm1_kernel() {
    extern __shared__ float sm[];
    float* sInvd = sm + 2 * G1BUF;
    float* sS2 = sInvd + 128;
    const int tid = threadIdx.x;
    const int qt = blockIdx.x >> 6, nt = blockIdx.x & 63;
    const int qbase = qt * 128, nbase = nt * 128;
    const u32 sb = smem_u32(sm);

    if (tid < 128) {
        sInvd[tid] = g_invd[qbase + tid];
        sS2[tid] = g_s2half[nbase + tid];
    }
    g1_load(tid, sb, qbase, nbase, 0);
    CP_COMMIT();

    const int wid = tid >> 5, lane = tid & 31;
    const int wm = wid >> 1, wn = wid & 1;
    const int gr = lane >> 2, lc = lane & 3;

    float acc[2][8][4];
    #pragma unroll
    for (int mb = 0; mb < 2; mb++)
        #pragma unroll
        for (int nb = 0; nb < 8; nb++)
            #pragma unroll
            for (int e = 0; e < 4; e++) acc[mb][nb][e] = 0.f;

    for (int s = 0; s < 8; s++) {
        const u32* buf = (const u32*)sm + (s & 1) * G1BUF;
        if (s + 1 < 8) {
            g1_load(tid, sb + (u32)(((s + 1) & 1) * G1BUF * 4), qbase, nbase,
                    (s + 1) * 32);
            CP_COMMIT();
            CP_WAIT1();
        } else {
            CP_WAIT0();
        }
        __syncthreads();
        const u32* Ah = buf;
        const u32* Al = buf + G1TILE;
        const u32* Bh = buf + 2 * G1TILE;
        const u32* Bl = buf + 3 * G1TILE;
        #pragma unroll
        for (int ks = 0; ks < 2; ks++) {
            int k0w = ks * 8;
            u32 ah[2][4], al[2][4];
            #pragma unroll
            for (int mb = 0; mb < 2; mb++) {
                int o0 = (wm * 32 + mb * 16 + gr) * G1W + k0w + lc;
                ah[mb][0] = Ah[o0];              ah[mb][1] = Ah[o0 + 8 * G1W];
                ah[mb][2] = Ah[o0 + 4];          ah[mb][3] = Ah[o0 + 8 * G1W + 4];
                al[mb][0] = Al[o0];              al[mb][1] = Al[o0 + 8 * G1W];
                al[mb][2] = Al[o0 + 4];          al[mb][3] = Al[o0 + 8 * G1W + 4];
            }
            u32 bh[8][2], bl[8][2];
            #pragma unroll
            for (int nb = 0; nb < 8; nb++) {
                int o = (wn * 64 + nb * 8 + gr) * G1W + k0w + lc;
                bh[nb][0] = Bh[o];
                bh[nb][1] = Bh[o + 4];
                bl[nb][0] = Bl[o];
                bl[nb][1] = Bl[o + 4];
            }
            #pragma unroll
            for (int mb = 0; mb < 2; mb++)
                #pragma unroll
                for (int nb = 0; nb < 8; nb++) {
                    MMA_BF16(acc[mb][nb], ah[mb], bh[nb]);
                    MMA_BF16(acc[mb][nb], ah[mb], bl[nb]);
                    MMA_BF16(acc[mb][nb], al[mb], bh[nb]);
                }
        }
        __syncthreads();
    }

    // epilogue: logits + row max
    float rmax[4] = {-3e38f, -3e38f, -3e38f, -3e38f};
    #pragma unroll
    for (int mb = 0; mb < 2; mb++) {
        int r0 = wm * 32 + mb * 16 + gr, r1 = r0 + 8;
        float inv0 = sInvd[r0], inv1 = sInvd[r1];
        #pragma unroll
        for (int nb = 0; nb < 8; nb++) {
            int n0 = wn * 64 + nb * 8 + 2 * lc;
            float s20 = sS2[n0], s21 = sS2[n0 + 1];
            float l00 = (acc[mb][nb][0] - s20) * inv0;
            float l01 = (acc[mb][nb][1] - s21) * inv0;
            float l10 = (acc[mb][nb][2] - s20) * inv1;
            float l11 = (acc[mb][nb][3] - s21) * inv1;
            *(float2*)&g_S[(long long)(qbase + r0) * NS + nbase + n0] =
                make_float2(l00, l01);
            *(float2*)&g_S[(long long)(qbase + r1) * NS + nbase + n0] =
                make_float2(l10, l11);
            rmax[2 * mb] = fmaxf(rmax[2 * mb], fmaxf(l00, l01));
            rmax[2 * mb + 1] = fmaxf(rmax[2 * mb + 1], fmaxf(l10, l11));
        }
    }
    #pragma unroll
    for (int i = 0; i < 4; i++) {
        rmax[i] = fmaxf(rmax[i], __shfl_xor_sync(0xffffffffu, rmax[i], 1));
        rmax[i] = fmaxf(rmax[i], __shfl_xor_sync(0xffffffffu, rmax[i], 2));
    }
    if (lc == 0) {
        #pragma unroll
        for (int mb = 0; mb < 2; mb++) {
            int r0 = wm * 32 + mb * 16 + gr;
            atomicMax(&g_mU[qbase + r0], fmap(rmax[2 * mb]));
            atomicMax(&g_mU[qbase + r0 + 8], fmap(rmax[2 * mb + 1]));
        }
    }
}

// ---------------- softmax: P = exp(logit - m) as bf16 high/low pair --------
__global__ __launch_bounds__(256) void softmax_kernel() {
    int q = blockIdx.x;
    int tid = threadIdx.x;
    unsigned mu = g_mU[q];
    float m = (mu & 0x80000000u) ? __uint_as_float(mu ^ 0x80000000u)
                                 : __uint_as_float(~mu);
    const float4* row = (const float4*)(g_S + (long long)q * NS);
    __nv_bfloat162* ph = (__nv_bfloat162*)(g_Ph + (long long)q * NS);
    __nv_bfloat162* pl = (__nv_bfloat162*)(g_Pl + (long long)q * NS);
    float sum = 0.f;
    #pragma unroll
    for (int i = tid; i < NS / 4; i += 256) {
        float4 v = row[i];
        float p0 = __expf(v.x - m), p1 = __expf(v.y - m);
        float p2 = __expf(v.z - m), p3 = __expf(v.w - m);
        __nv_bfloat16 h0 = __float2bfloat16(p0), h1 = __float2bfloat16(p1);
        __nv_bfloat16 h2 = __float2bfloat16(p2), h3 = __float2bfloat16(p3);
        ph[2 * i] = __nv_bfloat162(h0, h1);
        ph[2 * i + 1] = __nv_bfloat162(h2, h3);
        pl[2 * i] = __nv_bfloat162(
            __float2bfloat16(p0 - __bfloat162float(h0)),
            __float2bfloat16(p1 - __bfloat162float(h1)));
        pl[2 * i + 1] = __nv_bfloat162(
            __float2bfloat16(p2 - __bfloat162float(h2)),
            __float2bfloat16(p3 - __bfloat162float(h3)));
        sum += (p0 + p1) + (p2 + p3);
    }
    #pragma unroll
    for (int o = 16; o; o >>= 1) sum += __shfl_xor_sync(0xffffffffu, sum, o);
    __shared__ float red[8];
    if ((tid & 31) == 0) red[tid >> 5] = sum;
    __syncthreads();
    if (tid == 0) {
        float t = 0.f;
        #pragma unroll
        for (int i = 0; i < 8; i++) t += red[i];
        g_l[q] = t;
    }
}

// ---------------- GEMM2: O_part = P @ samples (bf16 3-product, split-K) ----
// CTA tile: 128 q x 128 d, K = 2048 samples in 64 chunks of 32.
static __device__ __forceinline__ void g2_load(int tid, u32 b, int qbase,
                                               int dbase, int kb) {
    #pragma unroll
    for (int it = 0; it < 8; it++) {
        int i = tid + it * 256;
        int sec = i >> 9, j = i & 511;
        int row = j >> 2, c = j & 3;   // c = 16B chunk (8 bf16)
        const __nv_bfloat16* src;
        if (sec == 0)      src = g_Ph + (long long)(qbase + row) * NS + kb + 8 * c;
        else if (sec == 1) src = g_Pl + (long long)(qbase + row) * NS + kb + 8 * c;
        else if (sec == 2) src = g_STh + (long long)(dbase + row) * NS + kb + 8 * c;
        else               src = g_STl + (long long)(dbase + row) * NS + kb + 8 * c;
        CP_ASYNC16(b + (u32)((sec * G1TILE + row * G1W + c * 4) * 4), src);
    }
}

__global__ __launch_bounds__(256, 2) void gemm2_kernel() {
    extern __shared__ float sm[];
    const int tid = threadIdx.x;
    const int qt = blockIdx.x >> 3;
    const int dt = (blockIdx.x >> 2) & 1;
    const int sp = blockIdx.x & 3;
    const int qbase = qt * 128, dbase = dt * 128, kb0 = sp * KSP;
    const u32 sb = smem_u32(sm);

    g2_load(tid, sb, qbase, dbase, kb0);
    CP_COMMIT();

    const int wid = tid >> 5, lane = tid & 31;
    const int wm = wid >> 1, wn = wid & 1;
    const int gr = lane >> 2, lc = lane & 3;

    float acc[2][8][4];
    #pragma unroll
    for (int mb = 0; mb < 2; mb++)
        #pragma unroll
        for (int nb = 0; nb < 8; nb++)
            #pragma unroll
            for (int e = 0; e < 4; e++) acc[mb][nb][e] = 0.f;

    for (int s = 0; s < KSP / 32; s++) {
        const u32* buf = (const u32*)sm + (s & 1) * G1BUF;
        if (s + 1 < KSP / 32) {
            g2_load(tid, sb + (u32)(((s + 1) & 1) * G1BUF * 4), qbase, dbase,
                    kb0 + (s + 1) * 32);
            CP_COMMIT();
            CP_WAIT1();
        } else {
            CP_WAIT0();
        }
        __syncthreads();
        const u32* Ph = buf;
        const u32* Pl = buf + G1TILE;
        const u32* Bh = buf + 2 * G1TILE;
        const u32* Bl = buf + 3 * G1TILE;
        #pragma unroll
        for (int ks = 0; ks < 2; ks++) {
            int k0w = ks * 8;
            u32 ah[2][4], al[2][4];
            #pragma unroll
            for (int mb = 0; mb < 2; mb++) {
                int o0 = (wm * 32 + mb * 16 + gr) * G1W + k0w + lc;
                ah[mb][0] = Ph[o0];              ah[mb][1] = Ph[o0 + 8 * G1W];
                ah[mb][2] = Ph[o0 + 4];          ah[mb][3] = Ph[o0 + 8 * G1W + 4];
                al[mb][0] = Pl[o0];              al[mb][1] = Pl[o0 + 8 * G1W];
                al[mb][2] = Pl[o0 + 4];          al[mb][3] = Pl[o0 + 8 * G1W + 4];
            }
            u32 bh[8][2], bl[8][2];
            #pragma unroll
            for (int nb = 0; nb < 8; nb++) {
                int o = (wn * 64 + nb * 8 + gr) * G1W + k0w + lc;
                bh[nb][0] = Bh[o];
                bh[nb][1] = Bh[o + 4];
                bl[nb][0] = Bl[o];
                bl[nb][1] = Bl[o + 4];
            }
            #pragma unroll
            for (int mb = 0; mb < 2; mb++)
                #pragma unroll
                for (int nb = 0; nb < 8; nb++) {
                    MMA_BF16(acc[mb][nb], ah[mb], bh[nb]);
                    MMA_BF16(acc[mb][nb], ah[mb], bl[nb]);
                    MMA_BF16(acc[mb][nb], al[mb], bh[nb]);
                }
        }
        __syncthreads();
    }

    // epilogue: store unnormalized O partials
    #pragma unroll
    for (int mb = 0; mb < 2; mb++) {
        int r0 = wm * 32 + mb * 16 + gr, r1 = r0 + 8;
        #pragma unroll
        for (int nb = 0; nb < 8; nb++) {
            int n0 = dbase + wn * 64 + nb * 8 + 2 * lc;
            *(float2*)&g_Op[sp][(qbase + r0) * DD + n0] =
                make_float2(acc[mb][nb][0], acc[mb][nb][1]);
            *(float2*)&g_Op[sp][(qbase + r1) * DD + n0] =
                make_float2(acc[mb][nb][2], acc[mb][nb][3]);
        }
    }
}

// ---------------- combine ----------------
__global__ void combine_kernel(const float* __restrict__ tvec,
                               const float* __restrict__ x,
                               float* __restrict__ out) {
    int idx = blockIdx.x * 256 + threadIdx.x;  // BQ * 64
    int q = idx >> 6, c4 = idx & 63;
    float linv = 1.0f / g_l[q];
    float tt = tvec[q];
    float ts = 0.01f * exp2f(tt * 13.287712379549449f);
    float scale = ts / fmaf(ts, ts, 1e-8f);
    float4 a = make_float4(0.f, 0.f, 0.f, 0.f);
    #pragma unroll
    for (int sp = 0; sp < NSPLIT; sp++) {
        float4 v = *(const float4*)(g_Op[sp] + q * DD + c4 * 4);
        a.x += v.x;
        a.y += v.y;
        a.z += v.z;
        a.w += v.w;
    }
    float4 xx = *(const float4*)(x + (long long)q * DD + c4 * 4);
    float4 r;
    r.x = (a.x * linv - xx.x) * scale;
    r.y = (a.y * linv - xx.y) * scale;
    r.z = (a.z * linv - xx.z) * scale;
    r.w = (a.w * linv - xx.w) * scale;
    *(float4*)(out + (long long)q * DD + c4 * 4) = r;
}

extern "C" void kernel_launch(void* const* d_in, const int* in_sizes, int n_in,
                              void* d_out, int out_size) {
    const float* t = nullptr;
    const float* x = nullptr;
    const float* s = nullptr;
    for (int i = 0; i < n_in; i++) {
        if (in_sizes[i] == BQ) t = (const float*)d_in[i];
        else if (in_sizes[i] == BQ * DD) x = (const float*)d_in[i];
        else if (in_sizes[i] == NS * DD) s = (const float*)d_in[i];
    }
    float* out = (float*)d_out;

    init_kernel<<<BQ / 256, 256>>>(t);
    split_x_kernel<<<BQ * DD / 256, 256>>>(x);
    transpose_kernel<<<dim3(NS / 32, DD / 32), dim3(32, 8)>>>(s);
    s2_kernel<<<NS / 8, 256>>>(s);

    cudaFuncSetAttribute(gemm1_kernel, cudaFuncAttributeMaxDynamicSharedMemorySize,
                         G1_SMEM);
    gemm1_kernel<<<(BQ / 128) * (NS / 128), 256, G1_SMEM>>>();

    softmax_kernel<<<BQ, 256>>>();

    cudaFuncSetAttribute(gemm2_kernel, cudaFuncAttributeMaxDynamicSharedMemorySize,
                         G2_SMEM);
    gemm2_kernel<<<(BQ / 128) * 2 * NSPLIT, 256, G2_SMEM>>>();

    combine_kernel<<<BQ * 64 / 256, 256>>>(t, x, out);
}

// round 16
// speedup vs baseline: 2.3847x; 1.0586x over previous
#include <cuda_runtime.h>
#include <cuda_bf16.h>

typedef unsigned int u32;
typedef unsigned long long u64;

#define BQ 4096
#define NS 8192
#define DD 256
#define NSPLIT 4
#define KSP (NS / NSPLIT)   // 2048 samples per split-K CTA

// ---------------- static scratch ----------------
__device__ __nv_bfloat16 g_Xh[BQ * DD];
__device__ __nv_bfloat16 g_Xl[BQ * DD];
__device__ __nv_bfloat16 g_Sh[NS * DD];
__device__ __nv_bfloat16 g_Sl[NS * DD];
__device__ __nv_bfloat16 g_STh[DD * NS];   // transposed samples bf16 high
__device__ __nv_bfloat16 g_STl[DD * NS];   // transposed samples bf16 low
__device__ float g_s2half[NS];
__device__ float g_invd[BQ];
__device__ unsigned g_mU[BQ];      // monotone-mapped row max
__device__ float g_l[BQ];
__device__ float g_S[(long long)BQ * NS];   // logits
__device__ float g_Op[NSPLIT][BQ * DD];

// ---------------- helpers ----------------
static __device__ __forceinline__ u32 smem_u32(const void* p) {
    return (u32)__cvta_generic_to_shared(p);
}
static __device__ __forceinline__ unsigned fmap(float v) {
    unsigned u = __float_as_uint(v);
    return (u & 0x80000000u) ? ~u : (u | 0x80000000u);
}
static __device__ __forceinline__ float funmap(unsigned u) {
    return (u & 0x80000000u) ? __uint_as_float(u ^ 0x80000000u)
                             : __uint_as_float(~u);
}
// split two fp32 into packed bf16x2 high + low parts (mma operand order)
static __device__ __forceinline__ void split2(float p0, float p1, u32& hi,
                                              u32& lo) {
    __nv_bfloat162 h = __floats2bfloat162_rn(p0, p1);
    u32 w = *(u32*)&h;
    float h0 = __uint_as_float(w << 16);
    float h1 = __uint_as_float(w & 0xffff0000u);
    __nv_bfloat162 l = __floats2bfloat162_rn(p0 - h0, p1 - h1);
    hi = w;
    lo = *(u32*)&l;
}

#define CP_ASYNC16(dst_u32, src_ptr)                                         \
    asm volatile("cp.async.cg.shared.global [%0], [%1], 16;" ::"r"(dst_u32), \
                 "l"(src_ptr))
#define CP_COMMIT() asm volatile("cp.async.commit_group;" ::: "memory")
#define CP_WAIT1() asm volatile("cp.async.wait_group 1;" ::: "memory")
#define CP_WAIT0() asm volatile("cp.async.wait_group 0;" ::: "memory")

// m16n8k16 bf16 mma: D += A*B (A row-major m16k16, B col-major k16n8)
#define MMA_BF16(d, a, b)                                                   \
    asm volatile(                                                           \
        "mma.sync.aligned.m16n8k16.row.col.f32.bf16.bf16.f32 "              \
        "{%0,%1,%2,%3}, {%4,%5,%6,%7}, {%8,%9}, {%0,%1,%2,%3};"             \
        : "+f"((d)[0]), "+f"((d)[1]), "+f"((d)[2]), "+f"((d)[3])            \
        : "r"((a)[0]), "r"((a)[1]), "r"((a)[2]), "r"((a)[3]),               \
          "r"((b)[0]), "r"((b)[1]))

// bf16 tiles: 32 bf16 per row = 16 words, padded stride 20 words:
// (20r + c) mod 32 over r=0..7, c=0..3 covers all 32 banks -> conflict-free.
#define G1W 20
#define G1TILE (128 * G1W)       // 2560 words per 128x32 bf16 tile
#define G1BUF (4 * G1TILE)       // 4 tiles = 10240 words
#define G1_SMEM ((2 * G1BUF + 256) * 4)

// gemm2 stage: fp32 logit tile (stride 40 = 8 mod 32 -> conflict-free
// float2 gathers per 16-lane phase) + Bh + Bl bf16 tiles.
#define LST 40
#define LG_TILE (128 * LST)                  // 5120 words
#define G2STAGE (LG_TILE + 2 * G1TILE)       // 10240 words = 40KB
#define G2_SMEM ((2 * G2STAGE + 128) * 4)

// ---------------- prep kernels ----------------
__global__ void init_kernel(const float* __restrict__ tvec) {
    int q = blockIdx.x * 256 + threadIdx.x;
    float tt = tvec[q];
    float ts = 0.01f * exp2f(tt * 13.287712379549449f);
    g_invd[q] = 1.0f / fmaf(ts, ts, 1e-8f);
    g_mU[q] = 0u;
    g_l[q] = 0.0f;
}

__global__ void split_x_kernel(const float* __restrict__ x) {
    int i = blockIdx.x * 256 + threadIdx.x;
    float v = x[i];
    __nv_bfloat16 h = __float2bfloat16(v);
    g_Xh[i] = h;
    g_Xl[i] = __float2bfloat16(v - __bfloat162float(h));
}

// samples: bf16 split row-major (gemm1) + bf16 split transposed (gemm2)
__global__ void transpose_kernel(const float* __restrict__ s) {
    __shared__ float T[32][33];
    int s0 = blockIdx.x * 32, d0 = blockIdx.y * 32;
    int tx = threadIdx.x, ty = threadIdx.y;  // (32, 8)
    #pragma unroll
    for (int j = 0; j < 32; j += 8) {
        long long idx = (long long)(s0 + ty + j) * DD + d0 + tx;
        float v = s[idx];
        T[ty + j][tx] = v;
        __nv_bfloat16 h = __float2bfloat16(v);
        g_Sh[idx] = h;
        g_Sl[idx] = __float2bfloat16(v - __bfloat162float(h));
    }
    __syncthreads();
    #pragma unroll
    for (int j = 0; j < 32; j += 8) {
        float v = T[tx][ty + j];
        long long o = (long long)(d0 + ty + j) * NS + s0 + tx;
        __nv_bfloat16 h = __float2bfloat16(v);
        g_STh[o] = h;
        g_STl[o] = __float2bfloat16(v - __bfloat162float(h));
    }
}

__global__ void s2_kernel(const float* __restrict__ samples) {
    int w = (blockIdx.x * blockDim.x + threadIdx.x) >> 5;
    int lane = threadIdx.x & 31;
    if (w >= NS) return;
    const float* row = samples + (size_t)w * DD;
    float s = 0.f;
    #pragma unroll
    for (int i = 0; i < DD / 32; i++) {
        float v = row[lane + 32 * i];
        s = fmaf(v, v, s);
    }
    #pragma unroll
    for (int o = 16; o; o >>= 1) s += __shfl_xor_sync(0xffffffffu, s, o);
    if (lane == 0) g_s2half[w] = 0.5f * s;
}

// ---------------- GEMM1: logits = (X @ S^T - s2half) * invd ----------------
static __device__ __forceinline__ void g1_load(int tid, u32 b, int qbase,
                                               int nbase, int kb) {
    #pragma unroll
    for (int it = 0; it < 8; it++) {
        int i = tid + it * 256;
        int sec = i >> 9, j = i & 511;
        int row = j >> 2, c = j & 3;   // c = 16B chunk (8 bf16)
        const __nv_bfloat16* src;
        if (sec == 0)      src = g_Xh + (size_t)(qbase + row) * DD + kb + 8 * c;
        else if (sec == 1) src = g_Xl + (size_t)(qbase + row) * DD + kb + 8 * c;
        else if (sec == 2) src = g_Sh + (size_t)(nbase + row) * DD + kb + 8 * c;
        else               src = g_Sl + (size_t)(nbase + row) * DD + kb + 8 * c;
        CP_ASYNC16(b + (u32)((sec * G1TILE + row * G1W + c * 4) * 4), src);
    }
}

__global__ __launch_bounds__(256, 2) void gemm1_kernel() {
    extern __shared__ float sm[];
    float* sInvd = sm + 2 * G1BUF;
    float* sS2 = sInvd + 128;
    const int tid = threadIdx.x;
    const int qt = blockIdx.x >> 6, nt = blockIdx.x & 63;
    const int qbase = qt * 128, nbase = nt * 128;
    const u32 sb = smem_u32(sm);

    if (tid < 128) {
        sInvd[tid] = g_invd[qbase + tid];
        sS2[tid] = g_s2half[nbase + tid];
    }
    g1_load(tid, sb, qbase, nbase, 0);
    CP_COMMIT();

    const int wid = tid >> 5, lane = tid & 31;
    const int wm = wid >> 1, wn = wid & 1;
    const int gr = lane >> 2, lc = lane & 3;

    float acc[2][8][4];
    #pragma unroll
    for (int mb = 0; mb < 2; mb++)
        #pragma unroll
        for (int nb = 0; nb < 8; nb++)
            #pragma unroll
            for (int e = 0; e < 4; e++) acc[mb][nb][e] = 0.f;

    for (int s = 0; s < 8; s++) {
        const u32* buf = (const u32*)sm + (s & 1) * G1BUF;
        if (s + 1 < 8) {
            g1_load(tid, sb + (u32)(((s + 1) & 1) * G1BUF * 4), qbase, nbase,
                    (s + 1) * 32);
            CP_COMMIT();
            CP_WAIT1();
        } else {
            CP_WAIT0();
        }
        __syncthreads();
        const u32* Ah = buf;
        const u32* Al = buf + G1TILE;
        const u32* Bh = buf + 2 * G1TILE;
        const u32* Bl = buf + 3 * G1TILE;
        #pragma unroll
        for (int ks = 0; ks < 2; ks++) {
            int k0w = ks * 8;
            u32 ah[2][4], al[2][4];
            #pragma unroll
            for (int mb = 0; mb < 2; mb++) {
                int o0 = (wm * 32 + mb * 16 + gr) * G1W + k0w + lc;
                ah[mb][0] = Ah[o0];              ah[mb][1] = Ah[o0 + 8 * G1W];
                ah[mb][2] = Ah[o0 + 4];          ah[mb][3] = Ah[o0 + 8 * G1W + 4];
                al[mb][0] = Al[o0];              al[mb][1] = Al[o0 + 8 * G1W];
                al[mb][2] = Al[o0 + 4];          al[mb][3] = Al[o0 + 8 * G1W + 4];
            }
            u32 bh[8][2], bl[8][2];
            #pragma unroll
            for (int nb = 0; nb < 8; nb++) {
                int o = (wn * 64 + nb * 8 + gr) * G1W + k0w + lc;
                bh[nb][0] = Bh[o];
                bh[nb][1] = Bh[o + 4];
                bl[nb][0] = Bl[o];
                bl[nb][1] = Bl[o + 4];
            }
            #pragma unroll
            for (int mb = 0; mb < 2; mb++)
                #pragma unroll
                for (int nb = 0; nb < 8; nb++) {
                    MMA_BF16(acc[mb][nb], ah[mb], bh[nb]);
                    MMA_BF16(acc[mb][nb], ah[mb], bl[nb]);
                    MMA_BF16(acc[mb][nb], al[mb], bh[nb]);
                }
        }
        __syncthreads();
    }

    // epilogue: logits + row max
    float rmax[4] = {-3e38f, -3e38f, -3e38f, -3e38f};
    #pragma unroll
    for (int mb = 0; mb < 2; mb++) {
        int r0 = wm * 32 + mb * 16 + gr, r1 = r0 + 8;
        float inv0 = sInvd[r0], inv1 = sInvd[r1];
        #pragma unroll
        for (int nb = 0; nb < 8; nb++) {
            int n0 = wn * 64 + nb * 8 + 2 * lc;
            float s20 = sS2[n0], s21 = sS2[n0 + 1];
            float l00 = (acc[mb][nb][0] - s20) * inv0;
            float l01 = (acc[mb][nb][1] - s21) * inv0;
            float l10 = (acc[mb][nb][2] - s20) * inv1;
            float l11 = (acc[mb][nb][3] - s21) * inv1;
            *(float2*)&g_S[(long long)(qbase + r0) * NS + nbase + n0] =
                make_float2(l00, l01);
            *(float2*)&g_S[(long long)(qbase + r1) * NS + nbase + n0] =
                make_float2(l10, l11);
            rmax[2 * mb] = fmaxf(rmax[2 * mb], fmaxf(l00, l01));
            rmax[2 * mb + 1] = fmaxf(rmax[2 * mb + 1], fmaxf(l10, l11));
        }
    }
    #pragma unroll
    for (int i = 0; i < 4; i++) {
        rmax[i] = fmaxf(rmax[i], __shfl_xor_sync(0xffffffffu, rmax[i], 1));
        rmax[i] = fmaxf(rmax[i], __shfl_xor_sync(0xffffffffu, rmax[i], 2));
    }
    if (lc == 0) {
        #pragma unroll
        for (int mb = 0; mb < 2; mb++) {
            int r0 = wm * 32 + mb * 16 + gr;
            atomicMax(&g_mU[qbase + r0], fmap(rmax[2 * mb]));
            atomicMax(&g_mU[qbase + r0 + 8], fmap(rmax[2 * mb + 1]));
        }
    }
}

// ------- GEMM2 (fused softmax): O_part = exp(logits - m) @ samples --------
// CTA tile: 128 q x 128 d, K = 2048 samples in 64 chunks of 32.
// Stage buffer: fp32 logit tile [128 x LST] + Bh + Bl bf16 operand tiles.
static __device__ __forceinline__ void g2_load(int tid, u32 b, int qbase,
                                               int dbase, int kb) {
    // logits: 128 rows x 8 16B-chunks
    #pragma unroll
    for (int it = 0; it < 4; it++) {
        int i = tid + it * 256;
        int row = i >> 3, c = i & 7;
        const float* src = g_S + (long long)(qbase + row) * NS + kb + 4 * c;
        CP_ASYNC16(b + (u32)((row * LST + c * 4) * 4), src);
    }
    // B tiles (d-major samples, bf16 high/low)
    #pragma unroll
    for (int it = 0; it < 4; it++) {
        int j = tid + it * 256;
        int sec = j >> 9, jj = j & 511;
        int row = jj >> 2, c = jj & 3;
        const __nv_bfloat16* src =
            (sec ? g_STl : g_STh) + (long long)(dbase + row) * NS + kb + 8 * c;
        CP_ASYNC16(b + (u32)((LG_TILE + sec * G1TILE + row * G1W + c * 4) * 4),
                   src);
    }
}

__global__ __launch_bounds__(256, 2) void gemm2_kernel() {
    extern __shared__ float sm[];
    float* sM = sm + 2 * G2STAGE;
    const int tid = threadIdx.x;
    const int qt = blockIdx.x >> 3;
    const int dt = (blockIdx.x >> 2) & 1;
    const int sp = blockIdx.x & 3;
    const int qbase = qt * 128, dbase = dt * 128, kb0 = sp * KSP;
    const u32 sb = smem_u32(sm);

    if (tid < 128) sM[tid] = funmap(g_mU[qbase + tid]);
    g2_load(tid, sb, qbase, dbase, kb0);
    CP_COMMIT();

    const int wid = tid >> 5, lane = tid & 31;
    const int wm = wid >> 1, wn = wid & 1;
    const int gr = lane >> 2, lc = lane & 3;

    float acc[2][8][4];
    #pragma unroll
    for (int mb = 0; mb < 2; mb++)
        #pragma unroll
        for (int nb = 0; nb < 8; nb++)
            #pragma unroll
            for (int e = 0; e < 4; e++) acc[mb][nb][e] = 0.f;
    float lsum[4] = {0.f, 0.f, 0.f, 0.f};

    __syncthreads();  // sM visible
    float mrow[4];
    #pragma unroll
    for (int mb = 0; mb < 2; mb++) {
        mrow[2 * mb] = sM[wm * 32 + mb * 16 + gr];
        mrow[2 * mb + 1] = sM[wm * 32 + mb * 16 + gr + 8];
    }

    for (int s = 0; s < KSP / 32; s++) {
        const float* Lg = sm + (s & 1) * G2STAGE;
        const u32* Bh = (const u32*)sm + (s & 1) * G2STAGE + LG_TILE;
        const u32* Bl = Bh + G1TILE;
        if (s + 1 < KSP / 32) {
            g2_load(tid, sb + (u32)(((s + 1) & 1) * G2STAGE * 4), qbase, dbase,
                    kb0 + (s + 1) * 32);
            CP_COMMIT();
            CP_WAIT1();
        } else {
            CP_WAIT0();
        }
        __syncthreads();
        #pragma unroll
        for (int ks = 0; ks < 2; ks++) {
            int k0w = ks * 8;          // bf16-tile word base
            int kw = ks * 16 + 2 * lc;  // fp32 logit col base
            u32 ah[2][4], al[2][4];
            #pragma unroll
            for (int mb = 0; mb < 2; mb++) {
                const float* L0 = Lg + (wm * 32 + mb * 16 + gr) * LST + kw;
                float2 f00 = *(const float2*)(L0);
                float2 f02 = *(const float2*)(L0 + 8);
                float2 f10 = *(const float2*)(L0 + 8 * LST);
                float2 f12 = *(const float2*)(L0 + 8 * LST + 8);
                float m0 = mrow[2 * mb], m1 = mrow[2 * mb + 1];
                float p00 = __expf(f00.x - m0), p01 = __expf(f00.y - m0);
                float p02 = __expf(f02.x - m0), p03 = __expf(f02.y - m0);
                float p10 = __expf(f10.x - m1), p11 = __expf(f10.y - m1);
                float p12 = __expf(f12.x - m1), p13 = __expf(f12.y - m1);
                lsum[2 * mb] += (p00 + p01) + (p02 + p03);
                lsum[2 * mb + 1] += (p10 + p11) + (p12 + p13);
                split2(p00, p01, ah[mb][0], al[mb][0]);
                split2(p10, p11, ah[mb][1], al[mb][1]);
                split2(p02, p03, ah[mb][2], al[mb][2]);
                split2(p12, p13, ah[mb][3], al[mb][3]);
            }
            u32 bh[8][2], bl[8][2];
            #pragma unroll
            for (int nb = 0; nb < 8; nb++) {
                int o = (wn * 64 + nb * 8 + gr) * G1W + k0w + lc;
                bh[nb][0] = Bh[o];
                bh[nb][1] = Bh[o + 4];
                bl[nb][0] = Bl[o];
                bl[nb][1] = Bl[o + 4];
            }
            #pragma unroll
            for (int mb = 0; mb < 2; mb++)
                #pragma unroll
                for (int nb = 0; nb < 8; nb++) {
                    MMA_BF16(acc[mb][nb], ah[mb], bh[nb]);
                    MMA_BF16(acc[mb][nb], ah[mb], bl[nb]);
                    MMA_BF16(acc[mb][nb], al[mb], bh[nb]);
                }
        }
        __syncthreads();
    }

    // l partials: one contribution per (row, sample-range); dt==0, wn==0 only
    #pragma unroll
    for (int i = 0; i < 4; i++) {
        lsum[i] += __shfl_xor_sync(0xffffffffu, lsum[i], 1);
        lsum[i] += __shfl_xor_sync(0xffffffffu, lsum[i], 2);
    }
    if (dt == 0 && wn == 0 && lc == 0) {
        #pragma unroll
        for (int mb = 0; mb < 2; mb++) {
            int r0 = wm * 32 + mb * 16 + gr;
            atomicAdd(&g_l[qbase + r0], lsum[2 * mb]);
            atomicAdd(&g_l[qbase + r0 + 8], lsum[2 * mb + 1]);
        }
    }

    // epilogue: store unnormalized O partials
    #pragma unroll
    for (int mb = 0; mb < 2; mb++) {
        int r0 = wm * 32 + mb * 16 + gr, r1 = r0 + 8;
        #pragma unroll
        for (int nb = 0; nb < 8; nb++) {
            int n0 = dbase + wn * 64 + nb * 8 + 2 * lc;
            *(float2*)&g_Op[sp][(qbase + r0) * DD + n0] =
                make_float2(acc[mb][nb][0], acc[mb][nb][1]);
            *(float2*)&g_Op[sp][(qbase + r1) * DD + n0] =
                make_float2(acc[mb][nb][2], acc[mb][nb][3]);
        }
    }
}

// ---------------- combine ----------------
__global__ void combine_kernel(const float* __restrict__ tvec,
                               const float* __restrict__ x,
                               float* __restrict__ out) {
    int idx = blockIdx.x * 256 + threadIdx.x;  // BQ * 64
    int q = idx >> 6, c4 = idx & 63;
    float linv = 1.0f / g_l[q];
    float tt = tvec[q];
    float ts = 0.01f * exp2f(tt * 13.287712379549449f);
    float scale = ts / fmaf(ts, ts, 1e-8f);
    float4 a = make_float4(0.f, 0.f, 0.f, 0.f);
    #pragma unroll
    for (int sp = 0; sp < NSPLIT; sp++) {
        float4 v = *(const float4*)(g_Op[sp] + q * DD + c4 * 4);
        a.x += v.x;
        a.y += v.y;
        a.z += v.z;
        a.w += v.w;
    }
    float4 xx = *(const float4*)(x + (long long)q * DD + c4 * 4);
    float4 r;
    r.x = (a.x * linv - xx.x) * scale;
    r.y = (a.y * linv - xx.y) * scale;
    r.z = (a.z * linv - xx.z) * scale;
    r.w = (a.w * linv - xx.w) * scale;
    *(float4*)(out + (long long)q * DD + c4 * 4) = r;
}

extern "C" void kernel_launch(void* const* d_in, const int* in_sizes, int n_in,
                              void* d_out, int out_size) {
    const float* t = nullptr;
    const float* x = nullptr;
    const float* s = nullptr;
    for (int i = 0; i < n_in; i++) {
        if (in_sizes[i] == BQ) t = (const float*)d_in[i];
        else if (in_sizes[i] == BQ * DD) x = (const float*)d_in[i];
        else if (in_sizes[i] == NS * DD) s = (const float*)d_in[i];
    }
    float* out = (float*)d_out;

    init_kernel<<<BQ / 256, 256>>>(t);
    split_x_kernel<<<BQ * DD / 256, 256>>>(x);
    transpose_kernel<<<dim3(NS / 32, DD / 32), dim3(32, 8)>>>(s);
    s2_kernel<<<NS / 8, 256>>>(s);

    cudaFuncSetAttribute(gemm1_kernel, cudaFuncAttributeMaxDynamicSharedMemorySize,
                         G1_SMEM);
    gemm1_kernel<<<(BQ / 128) * (NS / 128), 256, G1_SMEM>>>();

    cudaFuncSetAttribute(gemm2_kernel, cudaFuncAttributeMaxDynamicSharedMemorySize,
                         G2_SMEM);
    gemm2_kernel<<<(BQ / 128) * 2 * NSPLIT, 256, G2_SMEM>>>();

    combine_kernel<<<BQ * 64 / 256, 256>>>(t, x, out);
}

// round 17
// speedup vs baseline: 2.5188x; 1.0562x over previous
#include <cuda_runtime.h>
#include <cuda_bf16.h>

typedef unsigned int u32;
typedef unsigned long long u64;

#define BQ 4096
#define NS 8192
#define DD 256
#define NSPLIT 4
#define KSP (NS / NSPLIT)   // 2048 samples per split-K CTA

// ---------------- static scratch ----------------
__device__ __nv_bfloat16 g_Xh[BQ * DD];
__device__ __nv_bfloat16 g_Xl[BQ * DD];
__device__ __nv_bfloat16 g_Sh[NS * DD];
__device__ __nv_bfloat16 g_Sl[NS * DD];
__device__ __nv_bfloat16 g_STh[DD * NS];   // transposed samples bf16 high
__device__ __nv_bfloat16 g_STl[DD * NS];   // transposed samples bf16 low
__device__ float g_s2half[NS];
__device__ float g_invd[BQ];
__device__ unsigned g_mU[BQ];      // monotone-mapped row max
__device__ float g_l[BQ];
__device__ float g_S[(long long)BQ * NS];   // logits
__device__ float g_Op[NSPLIT][BQ * DD];

// ---------------- helpers ----------------
static __device__ __forceinline__ u32 smem_u32(const void* p) {
    return (u32)__cvta_generic_to_shared(p);
}
static __device__ __forceinline__ unsigned fmap(float v) {
    unsigned u = __float_as_uint(v);
    return (u & 0x80000000u) ? ~u : (u | 0x80000000u);
}
static __device__ __forceinline__ float funmap(unsigned u) {
    return (u & 0x80000000u) ? __uint_as_float(u ^ 0x80000000u)
                             : __uint_as_float(~u);
}
// split two fp32 into packed bf16x2 high + low parts (mma operand order)
static __device__ __forceinline__ void split2(float p0, float p1, u32& hi,
                                              u32& lo) {
    __nv_bfloat162 h = __floats2bfloat162_rn(p0, p1);
    u32 w = *(u32*)&h;
    float h0 = __uint_as_float(w << 16);
    float h1 = __uint_as_float(w & 0xffff0000u);
    __nv_bfloat162 l = __floats2bfloat162_rn(p0 - h0, p1 - h1);
    hi = w;
    lo = *(u32*)&l;
}

#define CP_ASYNC16(dst_u32, src_ptr)                                         \
    asm volatile("cp.async.cg.shared.global [%0], [%1], 16;" ::"r"(dst_u32), \
                 "l"(src_ptr))
#define CP_COMMIT() asm volatile("cp.async.commit_group;" ::: "memory")
#define CP_WAIT1() asm volatile("cp.async.wait_group 1;" ::: "memory")
#define CP_WAIT0() asm volatile("cp.async.wait_group 0;" ::: "memory")

// m16n8k16 bf16 mma: D += A*B (A row-major m16k16, B col-major k16n8)
#define MMA_BF16(d, a, b)                                                   \
    asm volatile(                                                           \
        "mma.sync.aligned.m16n8k16.row.col.f32.bf16.bf16.f32 "              \
        "{%0,%1,%2,%3}, {%4,%5,%6,%7}, {%8,%9}, {%0,%1,%2,%3};"             \
        : "+f"((d)[0]), "+f"((d)[1]), "+f"((d)[2]), "+f"((d)[3])            \
        : "r"((a)[0]), "r"((a)[1]), "r"((a)[2]), "r"((a)[3]),               \
          "r"((b)[0]), "r"((b)[1]))

// ldmatrix x4: 4 8x8 b16 matrices; per-lane row addresses (shared space)
#define LDSM4(r, a)                                                         \
    asm volatile(                                                           \
        "ldmatrix.sync.aligned.m8n8.x4.shared.b16 {%0,%1,%2,%3}, [%4];"     \
        : "=r"((r)[0]), "=r"((r)[1]), "=r"((r)[2]), "=r"((r)[3])            \
        : "r"(a))

// bf16 tiles: 32 bf16 per row = 16 words, padded stride 20 words:
// (20r + c) mod 32 over r=0..7, c=0..3 covers all 32 banks -> conflict-free,
// and 20r % 4 == 0 keeps every 16B chunk aligned for ldmatrix.
#define G1W 20
#define G1TILE (128 * G1W)       // 2560 words per 128x32 bf16 tile
#define G1BUF (4 * G1TILE)       // 4 tiles = 10240 words
#define G1_SMEM ((2 * G1BUF + 256) * 4)

// gemm2 stage: fp32 logit tile (stride 40 = 8 mod 32 -> conflict-free
// float2 gathers per 16-lane phase) + Bh + Bl bf16 tiles.
#define LST 40
#define LG_TILE (128 * LST)                  // 5120 words
#define G2STAGE (LG_TILE + 2 * G1TILE)       // 10240 words = 40KB
#define G2_SMEM ((2 * G2STAGE + 128) * 4)

// ---------------- prep kernels ----------------
__global__ void init_kernel(const float* __restrict__ tvec) {
    int q = blockIdx.x * 256 + threadIdx.x;
    float tt = tvec[q];
    float ts = 0.01f * exp2f(tt * 13.287712379549449f);
    g_invd[q] = 1.0f / fmaf(ts, ts, 1e-8f);
    g_mU[q] = 0u;
    g_l[q] = 0.0f;
}

__global__ void split_x_kernel(const float* __restrict__ x) {
    int i = blockIdx.x * 256 + threadIdx.x;
    float v = x[i];
    __nv_bfloat16 h = __float2bfloat16(v);
    g_Xh[i] = h;
    g_Xl[i] = __float2bfloat16(v - __bfloat162float(h));
}

// samples: bf16 split row-major (gemm1) + bf16 split transposed (gemm2)
__global__ void transpose_kernel(const float* __restrict__ s) {
    __shared__ float T[32][33];
    int s0 = blockIdx.x * 32, d0 = blockIdx.y * 32;
    int tx = threadIdx.x, ty = threadIdx.y;  // (32, 8)
    #pragma unroll
    for (int j = 0; j < 32; j += 8) {
        long long idx = (long long)(s0 + ty + j) * DD + d0 + tx;
        float v = s[idx];
        T[ty + j][tx] = v;
        __nv_bfloat16 h = __float2bfloat16(v);
        g_Sh[idx] = h;
        g_Sl[idx] = __float2bfloat16(v - __bfloat162float(h));
    }
    __syncthreads();
    #pragma unroll
    for (int j = 0; j < 32; j += 8) {
        float v = T[tx][ty + j];
        long long o = (long long)(d0 + ty + j) * NS + s0 + tx;
        __nv_bfloat16 h = __float2bfloat16(v);
        g_STh[o] = h;
        g_STl[o] = __float2bfloat16(v - __bfloat162float(h));
    }
}

__global__ void s2_kernel(const float* __restrict__ samples) {
    int w = (blockIdx.x * blockDim.x + threadIdx.x) >> 5;
    int lane = threadIdx.x & 31;
    if (w >= NS) return;
    const float* row = samples + (size_t)w * DD;
    float s = 0.f;
    #pragma unroll
    for (int i = 0; i < DD / 32; i++) {
        float v = row[lane + 32 * i];
        s = fmaf(v, v, s);
    }
    #pragma unroll
    for (int o = 16; o; o >>= 1) s += __shfl_xor_sync(0xffffffffu, s, o);
    if (lane == 0) g_s2half[w] = 0.5f * s;
}

// ---------------- GEMM1: logits = (X @ S^T - s2half) * invd ----------------
static __device__ __forceinline__ void g1_load(int tid, u32 b, int qbase,
                                               int nbase, int kb) {
    #pragma unroll
    for (int it = 0; it < 8; it++) {
        int i = tid + it * 256;
        int sec = i >> 9, j = i & 511;
        int row = j >> 2, c = j & 3;   // c = 16B chunk (8 bf16)
        const __nv_bfloat16* src;
        if (sec == 0)      src = g_Xh + (size_t)(qbase + row) * DD + kb + 8 * c;
        else if (sec == 1) src = g_Xl + (size_t)(qbase + row) * DD + kb + 8 * c;
        else if (sec == 2) src = g_Sh + (size_t)(nbase + row) * DD + kb + 8 * c;
        else               src = g_Sl + (size_t)(nbase + row) * DD + kb + 8 * c;
        CP_ASYNC16(b + (u32)((sec * G1TILE + row * G1W + c * 4) * 4), src);
    }
}

__global__ __launch_bounds__(256, 2) void gemm1_kernel() {
    extern __shared__ float sm[];
    float* sInvd = sm + 2 * G1BUF;
    float* sS2 = sInvd + 128;
    const int tid = threadIdx.x;
    const int qt = blockIdx.x >> 6, nt = blockIdx.x & 63;
    const int qbase = qt * 128, nbase = nt * 128;
    const u32 sb = smem_u32(sm);

    if (tid < 128) {
        sInvd[tid] = g_invd[qbase + tid];
        sS2[tid] = g_s2half[nbase + tid];
    }
    g1_load(tid, sb, qbase, nbase, 0);
    CP_COMMIT();

    const int wid = tid >> 5, lane = tid & 31;
    const int wm = wid >> 1, wn = wid & 1;
    const int gr = lane >> 2, lc = lane & 3;
    // ldmatrix per-lane address components
    const int a_row = lane & 15;             // m-row within 16-row fragment
    const int a_ch4 = (lane >> 4) << 2;      // k-chunk word offset (0 or 4)
    const int b_quad = lane >> 3;
    const int b_row = ((b_quad >> 1) << 3) + (lane & 7);  // n-row within pair
    const int b_ch4 = (b_quad & 1) << 2;

    float acc[2][8][4];
    #pragma unroll
    for (int mb = 0; mb < 2; mb++)
        #pragma unroll
        for (int nb = 0; nb < 8; nb++)
            #pragma unroll
            for (int e = 0; e < 4; e++) acc[mb][nb][e] = 0.f;

    for (int s = 0; s < 8; s++) {
        const u32 st = sb + (u32)((s & 1) * G1BUF * 4);
        if (s + 1 < 8) {
            g1_load(tid, sb + (u32)(((s + 1) & 1) * G1BUF * 4), qbase, nbase,
                    (s + 1) * 32);
            CP_COMMIT();
            CP_WAIT1();
        } else {
            CP_WAIT0();
        }
        __syncthreads();
        #pragma unroll
        for (int ks = 0; ks < 2; ks++) {
            int k0w = ks * 8;
            u32 ah[2][4], al[2][4];
            #pragma unroll
            for (int mb = 0; mb < 2; mb++) {
                u32 aw = st + (u32)((((wm * 32 + mb * 16 + a_row) * G1W) + k0w +
                                     a_ch4) * 4);
                LDSM4(ah[mb], aw);
                LDSM4(al[mb], aw + G1TILE * 4);
            }
            u32 bh[8][2], bl[8][2];
            #pragma unroll
            for (int p = 0; p < 4; p++) {
                u32 bw = st + (u32)((2 * G1TILE +
                                     (wn * 64 + p * 16 + b_row) * G1W + k0w +
                                     b_ch4) * 4);
                u32 r[4];
                LDSM4(r, bw);
                bh[2 * p][0] = r[0]; bh[2 * p][1] = r[1];
                bh[2 * p + 1][0] = r[2]; bh[2 * p + 1][1] = r[3];
                LDSM4(r, bw + G1TILE * 4);
                bl[2 * p][0] = r[0]; bl[2 * p][1] = r[1];
                bl[2 * p + 1][0] = r[2]; bl[2 * p + 1][1] = r[3];
            }
            #pragma unroll
            for (int mb = 0; mb < 2; mb++)
                #pragma unroll
                for (int nb = 0; nb < 8; nb++) {
                    MMA_BF16(acc[mb][nb], ah[mb], bh[nb]);
                    MMA_BF16(acc[mb][nb], ah[mb], bl[nb]);
                    MMA_BF16(acc[mb][nb], al[mb], bh[nb]);
                }
        }
        __syncthreads();
    }

    // epilogue: logits + row max
    float rmax[4] = {-3e38f, -3e38f, -3e38f, -3e38f};
    #pragma unroll
    for (int mb = 0; mb < 2; mb++) {
        int r0 = wm * 32 + mb * 16 + gr, r1 = r0 + 8;
        float inv0 = sInvd[r0], inv1 = sInvd[r1];
        #pragma unroll
        for (int nb = 0; nb < 8; nb++) {
            int n0 = wn * 64 + nb * 8 + 2 * lc;
            float s20 = sS2[n0], s21 = sS2[n0 + 1];
            float l00 = (acc[mb][nb][0] - s20) * inv0;
            float l01 = (acc[mb][nb][1] - s21) * inv0;
            float l10 = (acc[mb][nb][2] - s20) * inv1;
            float l11 = (acc[mb][nb][3] - s21) * inv1;
            *(float2*)&g_S[(long long)(qbase + r0) * NS + nbase + n0] =
                make_float2(l00, l01);
            *(float2*)&g_S[(long long)(qbase + r1) * NS + nbase + n0] =
                make_float2(l10, l11);
            rmax[2 * mb] = fmaxf(rmax[2 * mb], fmaxf(l00, l01));
            rmax[2 * mb + 1] = fmaxf(rmax[2 * mb + 1], fmaxf(l10, l11));
        }
    }
    #pragma unroll
    for (int i = 0; i < 4; i++) {
        rmax[i] = fmaxf(rmax[i], __shfl_xor_sync(0xffffffffu, rmax[i], 1));
        rmax[i] = fmaxf(rmax[i], __shfl_xor_sync(0xffffffffu, rmax[i], 2));
    }
    if (lc == 0) {
        #pragma unroll
        for (int mb = 0; mb < 2; mb++) {
            int r0 = wm * 32 + mb * 16 + gr;
            atomicMax(&g_mU[qbase + r0], fmap(rmax[2 * mb]));
            atomicMax(&g_mU[qbase + r0 + 8], fmap(rmax[2 * mb + 1]));
        }
    }
}

// ------- GEMM2 (fused softmax): O_part = exp(logits - m) @ samples --------
static __device__ __forceinline__ void g2_load(int tid, u32 b, int qbase,
                                               int dbase, int kb) {
    // logits: 128 rows x 8 16B-chunks
    #pragma unroll
    for (int it = 0; it < 4; it++) {
        int i = tid + it * 256;
        int row = i >> 3, c = i & 7;
        const float* src = g_S + (long long)(qbase + row) * NS + kb + 4 * c;
        CP_ASYNC16(b + (u32)((row * LST + c * 4) * 4), src);
    }
    // B tiles (d-major samples, bf16 high/low)
    #pragma unroll
    for (int it = 0; it < 4; it++) {
        int j = tid + it * 256;
        int sec = j >> 9, jj = j & 511;
        int row = jj >> 2, c = jj & 3;
        const __nv_bfloat16* src =
            (sec ? g_STl : g_STh) + (long long)(dbase + row) * NS + kb + 8 * c;
        CP_ASYNC16(b + (u32)((LG_TILE + sec * G1TILE + row * G1W + c * 4) * 4),
                   src);
    }
}

__global__ __launch_bounds__(256, 2) void gemm2_kernel() {
    extern __shared__ float sm[];
    float* sM = sm + 2 * G2STAGE;
    const int tid = threadIdx.x;
    const int qt = blockIdx.x >> 3;
    const int dt = (blockIdx.x >> 2) & 1;
    const int sp = blockIdx.x & 3;
    const int qbase = qt * 128, dbase = dt * 128, kb0 = sp * KSP;
    const u32 sb = smem_u32(sm);

    if (tid < 128) sM[tid] = funmap(g_mU[qbase + tid]);
    g2_load(tid, sb, qbase, dbase, kb0);
    CP_COMMIT();

    const int wid = tid >> 5, lane = tid & 31;
    const int wm = wid >> 1, wn = wid & 1;
    const int gr = lane >> 2, lc = lane & 3;
    const int b_quad = lane >> 3;
    const int b_row = ((b_quad >> 1) << 3) + (lane & 7);
    const int b_ch4 = (b_quad & 1) << 2;

    float acc[2][8][4];
    #pragma unroll
    for (int mb = 0; mb < 2; mb++)
        #pragma unroll
        for (int nb = 0; nb < 8; nb++)
            #pragma unroll
            for (int e = 0; e < 4; e++) acc[mb][nb][e] = 0.f;
    float lsum[4] = {0.f, 0.f, 0.f, 0.f};

    __syncthreads();  // sM visible
    float mrow[4];
    #pragma unroll
    for (int mb = 0; mb < 2; mb++) {
        mrow[2 * mb] = sM[wm * 32 + mb * 16 + gr];
        mrow[2 * mb + 1] = sM[wm * 32 + mb * 16 + gr + 8];
    }

    for (int s = 0; s < KSP / 32; s++) {
        const float* Lg = sm + (s & 1) * G2STAGE;
        const u32 st = sb + (u32)((s & 1) * G2STAGE * 4);
        if (s + 1 < KSP / 32) {
            g2_load(tid, sb + (u32)(((s + 1) & 1) * G2STAGE * 4), qbase, dbase,
                    kb0 + (s + 1) * 32);
            CP_COMMIT();
            CP_WAIT1();
        } else {
            CP_WAIT0();
        }
        __syncthreads();
        #pragma unroll
        for (int ks = 0; ks < 2; ks++) {
            int k0w = ks * 8;          // bf16-tile word base
            int kw = ks * 16 + 2 * lc;  // fp32 logit col base
            u32 ah[2][4], al[2][4];
            #pragma unroll
            for (int mb = 0; mb < 2; mb++) {
                const float* L0 = Lg + (wm * 32 + mb * 16 + gr) * LST + kw;
                float2 f00 = *(const float2*)(L0);
                float2 f02 = *(const float2*)(L0 + 8);
                float2 f10 = *(const float2*)(L0 + 8 * LST);
                float2 f12 = *(const float2*)(L0 + 8 * LST + 8);
                float m0 = mrow[2 * mb], m1 = mrow[2 * mb + 1];
                float p00 = __expf(f00.x - m0), p01 = __expf(f00.y - m0);
                float p02 = __expf(f02.x - m0), p03 = __expf(f02.y - m0);
                float p10 = __expf(f10.x - m1), p11 = __expf(f10.y - m1);
                float p12 = __expf(f12.x - m1), p13 = __expf(f12.y - m1);
                lsum[2 * mb] += (p00 + p01) + (p02 + p03);
                lsum[2 * mb + 1] += (p10 + p11) + (p12 + p13);
                split2(p00, p01, ah[mb][0], al[mb][0]);
                split2(p10, p11, ah[mb][1], al[mb][1]);
                split2(p02, p03, ah[mb][2], al[mb][2]);
                split2(p12, p13, ah[mb][3], al[mb][3]);
            }
            u32 bh[8][2], bl[8][2];
            #pragma unroll
            for (int p = 0; p < 4; p++) {
                u32 bw = st + (u32)((LG_TILE +
                                     (wn * 64 + p * 16 + b_row) * G1W + k0w +
                                     b_ch4) * 4);
                u32 r[4];
                LDSM4(r, bw);
                bh[2 * p][0] = r[0]; bh[2 * p][1] = r[1];
                bh[2 * p + 1][0] = r[2]; bh[2 * p + 1][1] = r[3];
                LDSM4(r, bw + G1TILE * 4);
                bl[2 * p][0] = r[0]; bl[2 * p][1] = r[1];
                bl[2 * p + 1][0] = r[2]; bl[2 * p + 1][1] = r[3];
            }
            #pragma unroll
            for (int mb = 0; mb < 2; mb++)
                #pragma unroll
                for (int nb = 0; nb < 8; nb++) {
                    MMA_BF16(acc[mb][nb], ah[mb], bh[nb]);
                    MMA_BF16(acc[mb][nb], ah[mb], bl[nb]);
                    MMA_BF16(acc[mb][nb], al[mb], bh[nb]);
                }
        }
        __syncthreads();
    }

    // l partials: one contribution per (row, sample-range); dt==0, wn==0 only
    #pragma unroll
    for (int i = 0; i < 4; i++) {
        lsum[i] += __shfl_xor_sync(0xffffffffu, lsum[i], 1);
        lsum[i] += __shfl_xor_sync(0xffffffffu, lsum[i], 2);
    }
    if (dt == 0 && wn == 0 && lc == 0) {
        #pragma unroll
        for (int mb = 0; mb < 2; mb++) {
            int r0 = wm * 32 + mb * 16 + gr;
            atomicAdd(&g_l[qbase + r0], lsum[2 * mb]);
            atomicAdd(&g_l[qbase + r0 + 8], lsum[2 * mb + 1]);
        }
    }

    // epilogue: store unnormalized O partials
    #pragma unroll
    for (int mb = 0; mb < 2; mb++) {
        int r0 = wm * 32 + mb * 16 + gr, r1 = r0 + 8;
        #pragma unroll
        for (int nb = 0; nb < 8; nb++) {
            int n0 = dbase + wn * 64 + nb * 8 + 2 * lc;
            *(float2*)&g_Op[sp][(qbase + r0) * DD + n0] =
                make_float2(acc[mb][nb][0], acc[mb][nb][1]);
            *(float2*)&g_Op[sp][(qbase + r1) * DD + n0] =
                make_float2(acc[mb][nb][2], acc[mb][nb][3]);
        }
    }
}

// ---------------- combine ----------------
__global__ void combine_kernel(const float* __restrict__ tvec,
                               const float* __restrict__ x,
                               float* __restrict__ out) {
    int idx = blockIdx.x * 256 + threadIdx.x;  // BQ * 64
    int q = idx >> 6, c4 = idx & 63;
    float linv = 1.0f / g_l[q];
    float tt = tvec[q];
    float ts = 0.01f * exp2f(tt * 13.287712379549449f);
    float scale = ts / fmaf(ts, ts, 1e-8f);
    float4 a = make_float4(0.f, 0.f, 0.f, 0.f);
    #pragma unroll
    for (int sp = 0; sp < NSPLIT; sp++) {
        float4 v = *(const float4*)(g_Op[sp] + q * DD + c4 * 4);
        a.x += v.x;
        a.y += v.y;
        a.z += v.z;
        a.w += v.w;
    }
    float4 xx = *(const float4*)(x + (long long)q * DD + c4 * 4);
    float4 r;
    r.x = (a.x * linv - xx.x) * scale;
    r.y = (a.y * linv - xx.y) * scale;
    r.z = (a.z * linv - xx.z) * scale;
    r.w = (a.w * linv - xx.w) * scale;
    *(float4*)(out + (long long)q * DD + c4 * 4) = r;
}

extern "C" void kernel_launch(void* const* d_in, const int* in_sizes, int n_in,
                              void* d_out, int out_size) {
    const float* t = nullptr;
    const float* x = nullptr;
    const float* s = nullptr;
    for (int i = 0; i < n_in; i++) {
        if (in_sizes[i] == BQ) t = (const float*)d_in[i];
        else if (in_sizes[i] == BQ * DD) x = (const float*)d_in[i];
        else if (in_sizes[i] == NS * DD) s = (const float*)d_in[i];
    }
    float* out = (float*)d_out;

    init_kernel<<<BQ / 256, 256>>>(t);
    split_x_kernel<<<BQ * DD / 256, 256>>>(x);
    transpose_kernel<<<dim3(NS / 32, DD / 32), dim3(32, 8)>>>(s);
    s2_kernel<<<NS / 8, 256>>>(s);

    cudaFuncSetAttribute(gemm1_kernel, cudaFuncAttributeMaxDynamicSharedMemorySize,
                         G1_SMEM);
    gemm1_kernel<<<(BQ / 128) * (NS / 128), 256, G1_SMEM>>>();

    cudaFuncSetAttribute(gemm2_kernel, cudaFuncAttributeMaxDynamicSharedMemorySize,
                         G2_SMEM);
    gemm2_kernel<<<(BQ / 128) * 2 * NSPLIT, 256, G2_SMEM>>>();

    combine_kernel<<<BQ * 64 / 256, 256>>>(t, x, out);
}